// round 12
// baseline (speedup 1.0000x reference)
#include <cuda_runtime.h>
#include <cuda_fp16.h>
#include <math.h>
#include <stdint.h>

#define B_ 32
#define T_ 512
#define V_ 8000
#define E_ 256
#define U_ 512
#define G4 (4*U_)     // 2048
#define BT (B_*T_)    // 16384
#define VPAD 8064
#define RH 8192       // rows per batch-half

#define ASTG 5120     // halves per A stage
#define BSTG 2048     // b32 per B stage
#define HROW 520      // h staging row stride (halves)

// ---------------- static device scratch ----------------
__device__ __half g_xh [BT*E_];
__device__ float  g_xw0[(size_t)BT*G4];
__device__ float  g_xw1[(size_t)BT*G4];
__device__ __half g_h1h[(size_t)BT*2*U_];
__device__ __half g_h2h[(size_t)BT*2*U_];
__device__ float  g_wr [2][2][U_*G4];            // [layer][dir]
__device__ __half g_hsh[2][2][B_*U_];            // [dir][parity]
__device__ __half2 g_wdP[(size_t)VPAD*2*U_/2];
__device__ __half2 g_k1P[2][(size_t)G4*E_/2];    // layer1 packed weights [dir]
__device__ __half2 g_k2P[2][(size_t)G4*2*U_/2];  // layer2 packed weights [dir]
__device__ unsigned g_gen[2];
__device__ unsigned g_cnt[2];

// ---------------- helpers ----------------
__device__ __forceinline__ uint32_t smem_u32(const void* p) {
    uint32_t a;
    asm("{ .reg .u64 t; cvta.to.shared.u64 t, %1; cvt.u32.u64 %0, t; }" : "=r"(a) : "l"(p));
    return a;
}
__device__ __forceinline__ void cp16(uint32_t dst, const void* src) {
    asm volatile("cp.async.ca.shared.global [%0], [%1], 16;" :: "r"(dst), "l"(src));
}
__device__ __forceinline__ void cp_commit() {
    asm volatile("cp.async.commit_group;" ::: "memory");
}
template <int N>
__device__ __forceinline__ void cp_wait() {
    asm volatile("cp.async.wait_group %0;" :: "n"(N) : "memory");
}
__device__ __forceinline__ void mma_f16(float c[4], const uint32_t a[4], uint32_t b0, uint32_t b1) {
    asm volatile(
        "mma.sync.aligned.m16n8k16.row.col.f32.f16.f16.f32 "
        "{%0,%1,%2,%3}, {%4,%5,%6,%7}, {%8,%9}, {%0,%1,%2,%3};"
        : "+f"(c[0]), "+f"(c[1]), "+f"(c[2]), "+f"(c[3])
        : "r"(a[0]), "r"(a[1]), "r"(a[2]), "r"(a[3]), "r"(b0), "r"(b1));
}
__device__ __forceinline__ void ldmat_x4(uint32_t r[4], uint32_t addr) {
    asm volatile("ldmatrix.sync.aligned.m8n8.x4.shared.b16 {%0,%1,%2,%3}, [%4];"
                 : "=r"(r[0]), "=r"(r[1]), "=r"(r[2]), "=r"(r[3]) : "r"(addr));
}

// ---------------- embedding gather -> fp16 ----------------
__global__ void embed_k(const int* __restrict__ tok, const float* __restrict__ emb) {
    int i = blockIdx.x * 256 + threadIdx.x;
    int row = i >> 5;
    int c8  = i & 31;
    int t = tok[row];
    const float4* s = (const float4*)(emb + (size_t)t * E_ + c8 * 8);
    float4 v0 = s[0], v1 = s[1];
    __half2 h[4];
    h[0] = __floats2half2_rn(v0.x, v0.y);
    h[1] = __floats2half2_rn(v0.z, v0.w);
    h[2] = __floats2half2_rn(v1.x, v1.y);
    h[3] = __floats2half2_rn(v1.z, v1.w);
    *(uint4*)&g_xh[(size_t)row * E_ + c8 * 8] = *(uint4*)h;
}

// ---------------- Wr reorder: [k][g*U+u] -> [k][u*4+g], per layer ----------------
__global__ void reorder_k(const float* __restrict__ rf, const float* __restrict__ rb,
                          int layer) {
    int i = blockIdx.x * 256 + threadIdx.x;
    int k = i / G4;
    int c = i % G4;
    int u = c >> 2, g = c & 3;
    g_wr[layer][0][i] = rf[(size_t)k * G4 + g * U_ + u];
    g_wr[layer][1][i] = rb[(size_t)k * G4 + g * U_ + u];
}

// ---------------- pack B[K][N] -> fp16 fragment order ----------------
__global__ void pack_b_k(const float* __restrict__ in, __half2* __restrict__ out,
                         int K, int N) {
    size_t o = (size_t)blockIdx.x * 256 + threadIdx.x;
    int per_bc = K * 64;
    int bc  = (int)(o / per_bc);
    int rem = (int)(o % per_bc);
    int kt = rem >> 10;
    int r2 = rem & 1023;
    int pg = r2 >> 7;
    int lr = r2 & 127;
    int lane = lr >> 2, r = lr & 3;
    int nt = 2*pg + (r >> 1);
    int breg = r & 1;
    int g = lane >> 2, t4 = lane & 3;
    int k = kt*16 + breg*8 + 2*t4;
    int n = bc*128 + nt*8 + g;
    float v0 = (n < N) ? in[(size_t)k * N + n] : 0.f;
    float v1 = (n < N) ? in[(size_t)(k+1) * N + n] : 0.f;
    out[o] = __floats2half2_rn(v0, v1);
}

// ---------------- fp16 mma GEMM with row offset ----------------
__global__ __launch_bounds__(256)
void f16_gemm_k(const __half* __restrict__ Ah, const __half2* __restrict__ Bp,
                const float* __restrict__ bias, float* __restrict__ C,
                int N, int K, int rowOff)
{
    extern __shared__ __half sm[];
    __half* As = sm;
    uint32_t* Bs = (uint32_t*)(sm + 4*ASTG);

    int tid = threadIdx.x;
    int wid = tid >> 5, lane = tid & 31;
    int wm = wid >> 1, wn = wid & 1;
    int gid = lane >> 2, tg = lane & 3;
    int rowBase = blockIdx.y * 128 + rowOff;
    int bc = blockIdx.x;
    int colBase = bc * 128;
    const uint32_t* Bsrc = (const uint32_t*)Bp + (size_t)bc * K * 64;

    float c[2][8][4];
#pragma unroll
    for (int i = 0; i < 2; i++)
#pragma unroll
        for (int j = 0; j < 8; j++)
#pragma unroll
            for (int q = 0; q < 4; q++) c[i][j][q] = 0.f;

    const int nc = K >> 5;

    auto stage = [&](int chunk, int slot) {
#pragma unroll
        for (int it = 0; it < 2; it++) {
            int idx = it * 256 + tid;
            int row = idx >> 2, cq = idx & 3;
            cp16(smem_u32(&As[slot*ASTG + row*40 + cq*8]),
                 Ah + (size_t)(rowBase + row) * K + chunk*32 + cq*8);
            cp16(smem_u32(&Bs[slot*BSTG + idx*4]),
                 Bsrc + (size_t)chunk * BSTG + idx*4);
        }
    };

    stage(0, 0); cp_commit();
    stage(1, 1); cp_commit();

    for (int i = 0; i < nc; i++) {
        if (i + 2 < nc) stage(i + 2, (i + 2) & 3);
        cp_commit();
        cp_wait<2>();
        __syncthreads();

        int slot = i & 3;
        const uint32_t* Au = (const uint32_t*)&As[slot*ASTG];
        const uint32_t* Bu = &Bs[slot*BSTG];
#pragma unroll
        for (int kk = 0; kk < 2; kk++) {
            uint32_t af[2][4];
#pragma unroll
            for (int mt = 0; mt < 2; mt++) {
                int rb = (wm*32 + mt*16 + gid)*20 + kk*8 + tg;
                af[mt][0] = Au[rb];
                af[mt][1] = Au[rb + 160];
                af[mt][2] = Au[rb + 4];
                af[mt][3] = Au[rb + 164];
            }
#pragma unroll
            for (int p = 0; p < 4; p++) {
                uint4 bv = *(const uint4*)&Bu[kk*1024 + ((wn*4 + p)*32 + lane)*4];
                mma_f16(c[0][2*p],   af[0], bv.x, bv.y);
                mma_f16(c[0][2*p+1], af[0], bv.z, bv.w);
                mma_f16(c[1][2*p],   af[1], bv.x, bv.y);
                mma_f16(c[1][2*p+1], af[1], bv.z, bv.w);
            }
        }
    }

#pragma unroll
    for (int mt = 0; mt < 2; mt++) {
        int r0 = rowBase + wm*32 + mt*16 + gid;
#pragma unroll
        for (int nb = 0; nb < 8; nb++) {
            int col = colBase + wn*64 + nb*8 + tg*2;
            if (col < N) {
                float b0 = bias[col], b1 = bias[col + 1];
                *(float2*)&C[(size_t)r0 * N + col] =
                    make_float2(c[mt][nb][0] + b0, c[mt][nb][1] + b1);
                *(float2*)&C[(size_t)(r0 + 8) * N + col] =
                    make_float2(c[mt][nb][2] + b0, c[mt][nb][3] + b1);
            }
        }
    }
}

// ---------------- software grid barrier (64 CTAs per dir) ----------------
__device__ __forceinline__ void grid_barrier(int dir) {
    __syncthreads();
    if (threadIdx.x == 0) {
        __threadfence();
        volatile unsigned* gen = &g_gen[dir];
        unsigned old = *gen;
        unsigned a = atomicAdd(&g_cnt[dir], 1u);
        if (a == 63u) {
            g_cnt[dir] = 0u;
            __threadfence();
            *gen = old + 1u;
        } else {
            while (*gen == old) { }
        }
        __threadfence();
    }
    __syncthreads();
}

// ---------------- persistent bidirectional LSTM, 16-batch half ----------------
// 128 CTAs: dir = bid>>6, ub = bid&63 (8 units). 128 threads = 4 warps.
// Per step: C[16b, 32cols] = h[16,512](fp16) @ WrSlice. Warp w: cols [8w, 8w+8).
__global__ __launch_bounds__(128)
void lstm_half_k(const float* __restrict__ xwf, const float* __restrict__ xwb,
                 const int* __restrict__ tok, __half* __restrict__ y,
                 int layer, int bOff)
{
    extern __shared__ __half smh[];
    uint32_t* swB = (uint32_t*)smh;              // 8192 uint32 = 32 KB B-frags
    __half*   shh = smh + 16384;                 // 16 x HROW halves staged h

    int dir = blockIdx.x >> 6;
    int ub  = blockIdx.x & 63;
    int u0  = ub * 8;
    int tid = threadIdx.x;
    int w   = tid >> 5, lane = tid & 31;
    int gid = lane >> 2, tg = lane & 3;

    const float* xw = dir ? xwb : xwf;
    const float* wr = g_wr[layer][dir];

    // ---- pack Wr slice into B-fragment order (once) ----
    for (int i = tid; i < 8192; i += 128) {
        int r  = i & 1;
        int ln = (i >> 1) & 31;
        int w_ = (i >> 6) & 3;
        int kt = i >> 8;
        int n = w_*8 + (ln >> 2);
        int k = kt*16 + r*8 + 2*(ln & 3);
        __half2 hv = __floats2half2_rn(wr[(size_t)k * G4 + u0*4 + n],
                                       wr[(size_t)(k+1) * G4 + u0*4 + n]);
        swB[i] = *(uint32_t*)&hv;
    }
    // zero initial h (parity 0) for our units/batches
    for (int i = tid; i < 128; i += 128) {
        int bb = i >> 3;
        g_hsh[dir][0][(bOff + bb) * U_ + u0 + (i & 7)] = __float2half_rn(0.f);
    }

    int uu = u0 + w*2 + (tg >> 1);
    float cst[2] = {0.f, 0.f};
    float hst[2] = {0.f, 0.f};

    __threadfence();
    grid_barrier(dir);

    for (int s = 0; s < T_; s++) {
        int t = dir ? (T_ - 1 - s) : s;
        const __half* hread  = g_hsh[dir][s & 1];
        __half*       hwrite = g_hsh[dir][(s & 1) ^ 1];

        // ---- prefetch xw gates + masks ----
        float xwv[2][2];
        int   msk[2];
#pragma unroll
        for (int j = 0; j < 2; j++) {
            int b = bOff + gid + j*8;
            msk[j] = tok[b * T_ + t];
#pragma unroll
            for (int c = 0; c < 2; c++) {
                int col = w*8 + 2*tg + c;
                int gg = col & 3;
                int uc = u0 + (col >> 2);
                xwv[c][j] = xw[((size_t)b * T_ + t) * G4 + gg * U_ + uc];
            }
        }

        // ---- stage h fp16 into SMEM (16 rows) ----
        for (int i = tid; i < 1024; i += 128) {
            int row = i >> 6, ch = i & 63;
            cp16(smem_u32(&shh[row * HROW + ch * 8]),
                 hread + (bOff + row) * U_ + ch * 8);
        }
        cp_commit();
        cp_wait<0>();
        __syncthreads();

        // ---- mma mainloop: 32 k-steps, one m16n8k16 each ----
        float acc[4] = {0.f, 0.f, 0.f, 0.f};
        int r8 = lane & 7;
        int quad = lane >> 3;
        uint32_t abase = smem_u32(&shh[((quad & 1)*8 + r8) * HROW + (quad >> 1)*8]);

#pragma unroll 8
        for (int kt = 0; kt < 32; kt++) {
            uint32_t a[4];
            ldmat_x4(a, abase + kt*32);
            uint2 bv = *(const uint2*)&swB[(kt*4 + w)*64 + lane*2];
            mma_f16(acc, a, bv.x, bv.y);
        }

        // ---- add xw, pair-exchange, cell update ----
        float z[4];
#pragma unroll
        for (int q = 0; q < 4; q++)
            z[q] = acc[q] + xwv[q & 1][q >> 1];

        float rz[4];
#pragma unroll
        for (int q = 0; q < 4; q++)
            rz[q] = __shfl_xor_sync(0xffffffffu, z[q], 1);

        if ((tg & 1) == 0) {
#pragma unroll
            for (int j = 0; j < 2; j++) {
                float zi = z [2*j], zf = z [2*j + 1];
                float zg = rz[2*j], zo = rz[2*j + 1];
                float ig = 1.f / (1.f + expf(-zi));
                float fg = 1.f / (1.f + expf(-zf));
                float gg = tanhf(zg);
                float og = 1.f / (1.f + expf(-zo));
                float cn = fg * cst[j] + ig * gg;
                float hn = og * tanhf(cn);
                if (msk[j] != 0) { cst[j] = cn; hst[j] = hn; }
                int b = bOff + gid + j*8;
                __half hh = __float2half_rn(hst[j]);
                hwrite[b * U_ + uu] = hh;
                y[((size_t)b * T_ + t) * (2*U_) + dir * U_ + uu] = hh;
            }
        }

        __threadfence();
        grid_barrier(dir);
    }
}

// ---------------- streams/events (created at load time, before mem baseline) ----
static cudaStream_t g_s2;
static cudaEvent_t  g_ev[10];
static struct InitStreams {
    InitStreams() {
        cudaStreamCreateWithFlags(&g_s2, cudaStreamNonBlocking);
        for (int i = 0; i < 10; i++)
            cudaEventCreateWithFlags(&g_ev[i], cudaEventDisableTiming);
    }
} g_initStreams;

// ---------------- host ----------------
extern "C" void kernel_launch(void* const* d_in, const int* in_sizes, int n_in,
                              void* d_out, int out_size)
{
    const int*   tokens = (const int*)  d_in[0];
    const float* emb    = (const float*)d_in[1];
    const float* k1f    = (const float*)d_in[2];
    const float* r1f    = (const float*)d_in[3];
    const float* b1f    = (const float*)d_in[4];
    const float* k1b    = (const float*)d_in[5];
    const float* r1b    = (const float*)d_in[6];
    const float* b1b    = (const float*)d_in[7];
    const float* k2f    = (const float*)d_in[8];
    const float* r2f    = (const float*)d_in[9];
    const float* b2f    = (const float*)d_in[10];
    const float* k2b    = (const float*)d_in[11];
    const float* r2b    = (const float*)d_in[12];
    const float* b2b    = (const float*)d_in[13];
    const float* wd     = (const float*)d_in[14];
    const float* bd     = (const float*)d_in[15];
    float* out = (float*)d_out;

    static __half *pxh = nullptr, *ph1h, *ph2h;
    static float *pxw0, *pxw1;
    static __half2 *pwdP, *pk1P0, *pk1P1, *pk2P0, *pk2P1;
    if (!pxh) {
        cudaGetSymbolAddress((void**)&pxh,  g_xh);
        cudaGetSymbolAddress((void**)&pxw0, g_xw0);
        cudaGetSymbolAddress((void**)&pxw1, g_xw1);
        cudaGetSymbolAddress((void**)&ph1h, g_h1h);
        cudaGetSymbolAddress((void**)&ph2h, g_h2h);
        cudaGetSymbolAddress((void**)&pwdP, g_wdP);
        cudaGetSymbolAddress((void**)&pk1P0, g_k1P);
        pk1P1 = pk1P0 + (size_t)G4 * E_ / 2;
        cudaGetSymbolAddress((void**)&pk2P0, g_k2P);
        pk2P1 = pk2P0 + (size_t)G4 * 2 * U_ / 2;
        cudaFuncSetAttribute(lstm_half_k,
                             cudaFuncAttributeMaxDynamicSharedMemorySize,
                             32768 + 16*HROW*2);
        cudaFuncSetAttribute(f16_gemm_k,
                             cudaFuncAttributeMaxDynamicSharedMemorySize,
                             4*ASTG*2 + 4*BSTG*4);
    }
    const int lsm = 32768 + 16*HROW*2;
    const int gsm = 4*ASTG*2 + 4*BSTG*4;

    cudaEvent_t EA    = g_ev[0], EB    = g_ev[1], EL1P = g_ev[2];
    cudaEvent_t EXW2P = g_ev[3], EL1Q  = g_ev[4], EL2P = g_ev[5];
    cudaEvent_t EXW2Q = g_ev[6], EL2Q  = g_ev[7], EF   = g_ev[8];

    // ---- prep on main stream ----
    embed_k<<<(BT*E_/8)/256, 256>>>(tokens, emb);
    pack_b_k<<<(G4*E_/2)/256, 256>>>(k1f, pk1P0, E_, G4);
    reorder_k<<<(U_*G4)/256, 256>>>(r1f, r1b, 0);
    reorder_k<<<(U_*G4)/256, 256>>>(r2f, r2b, 1);
    pack_b_k<<<(G4*E_/2)/256, 256>>>(k1b, pk1P1, E_, G4);
    cudaEventRecord(EA, 0);

    // ---- s2: remaining packs + xW1_Q ----
    cudaStreamWaitEvent(g_s2, EA, 0);
    pack_b_k<<<(G4*2*U_/2)/256, 256, 0, g_s2>>>(k2f, pk2P0, 2*U_, G4);
    pack_b_k<<<(G4*2*U_/2)/256, 256, 0, g_s2>>>(k2b, pk2P1, 2*U_, G4);
    pack_b_k<<<((size_t)VPAD*2*U_/2)/256, 256, 0, g_s2>>>(wd, pwdP, 2*U_, V_);
    f16_gemm_k<<<dim3(16, 64), 256, gsm, g_s2>>>(pxh, pk1P0, b1f, pxw0, G4, E_, RH);
    f16_gemm_k<<<dim3(16, 64), 256, gsm, g_s2>>>(pxh, pk1P1, b1b, pxw1, G4, E_, RH);
    cudaEventRecord(EB, g_s2);

    // ---- main: xW1_P + lstm1_P ----
    f16_gemm_k<<<dim3(16, 64), 256, gsm>>>(pxh, pk1P0, b1f, pxw0, G4, E_, 0);
    f16_gemm_k<<<dim3(16, 64), 256, gsm>>>(pxh, pk1P1, b1b, pxw1, G4, E_, 0);
    lstm_half_k<<<128, 128, lsm>>>(pxw0, pxw1, tokens, ph1h, 0, 0);
    cudaEventRecord(EL1P, 0);

    // ---- s2: xW2_P (needs h1 rows P) ----
    cudaStreamWaitEvent(g_s2, EL1P, 0);
    f16_gemm_k<<<dim3(16, 64), 256, gsm, g_s2>>>(ph1h, pk2P0, b2f, pxw0, G4, 2*U_, 0);
    f16_gemm_k<<<dim3(16, 64), 256, gsm, g_s2>>>(ph1h, pk2P1, b2b, pxw1, G4, 2*U_, 0);
    cudaEventRecord(EXW2P, g_s2);

    // ---- main: lstm1_Q (needs xW1_Q) ----
    cudaStreamWaitEvent(0, EB, 0);
    lstm_half_k<<<128, 128, lsm>>>(pxw0, pxw1, tokens, ph1h, 0, 16);
    cudaEventRecord(EL1Q, 0);

    // ---- s2: xW2_Q (needs h1 rows Q) ----
    cudaStreamWaitEvent(g_s2, EL1Q, 0);
    f16_gemm_k<<<dim3(16, 64), 256, gsm, g_s2>>>(ph1h, pk2P0, b2f, pxw0, G4, 2*U_, RH);
    f16_gemm_k<<<dim3(16, 64), 256, gsm, g_s2>>>(ph1h, pk2P1, b2b, pxw1, G4, 2*U_, RH);
    cudaEventRecord(EXW2Q, g_s2);

    // ---- main: lstm2_P (needs xW2_P) ----
    cudaStreamWaitEvent(0, EXW2P, 0);
    lstm_half_k<<<128, 128, lsm>>>(pxw0, pxw1, tokens, ph2h, 1, 0);
    cudaEventRecord(EL2P, 0);

    // ---- s2: logits_P (needs h2 rows P) ----
    cudaStreamWaitEvent(g_s2, EL2P, 0);
    f16_gemm_k<<<dim3(63, 64), 256, gsm, g_s2>>>(ph2h, pwdP, bd, out, V_, 2*U_, 0);

    // ---- main: lstm2_Q (needs xW2_Q) ----
    cudaStreamWaitEvent(0, EXW2Q, 0);
    lstm_half_k<<<128, 128, lsm>>>(pxw0, pxw1, tokens, ph2h, 1, 16);
    cudaEventRecord(EL2Q, 0);

    // ---- s2: logits_Q, then join ----
    cudaStreamWaitEvent(g_s2, EL2Q, 0);
    f16_gemm_k<<<dim3(63, 64), 256, gsm, g_s2>>>(ph2h, pwdP, bd, out, V_, 2*U_, RH);
    cudaEventRecord(EF, g_s2);
    cudaStreamWaitEvent(0, EF, 0);
}

// round 13
// speedup vs baseline: 1.8772x; 1.8772x over previous
#include <cuda_runtime.h>
#include <cuda_fp16.h>
#include <math.h>
#include <stdint.h>

#define B_ 32
#define T_ 512
#define V_ 8000
#define E_ 256
#define U_ 512
#define G4 (4*U_)     // 2048
#define BT (B_*T_)    // 16384
#define VPAD 8064
#define SPLIT 384     // LSTM T-split point

#define ASTG 5120     // halves per A stage
#define BSTG 2048     // b32 per B stage
#define HROW 520      // h staging row stride (halves)

// ---------------- static device scratch ----------------
__device__ __half g_xh [BT*E_];
__device__ float  g_xw0[(size_t)BT*G4];
__device__ float  g_xw1[(size_t)BT*G4];
__device__ __half g_h1h[(size_t)BT*2*U_];
__device__ __half g_h2h[(size_t)BT*2*U_];
__device__ float  g_wr [2][2][U_*G4];            // [layer][dir]
__device__ __half g_hsh[2][2][B_*U_];            // [dir][parity]
__device__ float  g_cs [2][B_*U_];               // persisted c state [dir]
__device__ __half2 g_wdP[(size_t)VPAD*2*U_/2];
__device__ __half2 g_k1P[2][(size_t)G4*E_/2];
__device__ __half2 g_k2P[2][(size_t)G4*2*U_/2];
__device__ unsigned g_gen[2];
__device__ unsigned g_cnt[2];

// ---------------- helpers ----------------
__device__ __forceinline__ uint32_t smem_u32(const void* p) {
    uint32_t a;
    asm("{ .reg .u64 t; cvta.to.shared.u64 t, %1; cvt.u32.u64 %0, t; }" : "=r"(a) : "l"(p));
    return a;
}
__device__ __forceinline__ void cp16(uint32_t dst, const void* src) {
    asm volatile("cp.async.ca.shared.global [%0], [%1], 16;" :: "r"(dst), "l"(src));
}
__device__ __forceinline__ void cp_commit() {
    asm volatile("cp.async.commit_group;" ::: "memory");
}
template <int N>
__device__ __forceinline__ void cp_wait() {
    asm volatile("cp.async.wait_group %0;" :: "n"(N) : "memory");
}
__device__ __forceinline__ void mma_f16(float c[4], const uint32_t a[4], uint32_t b0, uint32_t b1) {
    asm volatile(
        "mma.sync.aligned.m16n8k16.row.col.f32.f16.f16.f32 "
        "{%0,%1,%2,%3}, {%4,%5,%6,%7}, {%8,%9}, {%0,%1,%2,%3};"
        : "+f"(c[0]), "+f"(c[1]), "+f"(c[2]), "+f"(c[3])
        : "r"(a[0]), "r"(a[1]), "r"(a[2]), "r"(a[3]), "r"(b0), "r"(b1));
}
__device__ __forceinline__ void ldmat_x4(uint32_t r[4], uint32_t addr) {
    asm volatile("ldmatrix.sync.aligned.m8n8.x4.shared.b16 {%0,%1,%2,%3}, [%4];"
                 : "=r"(r[0]), "=r"(r[1]), "=r"(r[2]), "=r"(r[3]) : "r"(addr));
}
__device__ __forceinline__ float sigf(float x) {
    return __fdividef(1.f, 1.f + __expf(-x));
}
__device__ __forceinline__ float tanhfast(float x) {
    return fmaf(2.f, sigf(2.f * x), -1.f);
}

// ---------------- embedding gather -> fp16 ----------------
__global__ void embed_k(const int* __restrict__ tok, const float* __restrict__ emb) {
    int i = blockIdx.x * 256 + threadIdx.x;
    int row = i >> 5;
    int c8  = i & 31;
    int t = tok[row];
    const float4* s = (const float4*)(emb + (size_t)t * E_ + c8 * 8);
    float4 v0 = s[0], v1 = s[1];
    __half2 h[4];
    h[0] = __floats2half2_rn(v0.x, v0.y);
    h[1] = __floats2half2_rn(v0.z, v0.w);
    h[2] = __floats2half2_rn(v1.x, v1.y);
    h[3] = __floats2half2_rn(v1.z, v1.w);
    *(uint4*)&g_xh[(size_t)row * E_ + c8 * 8] = *(uint4*)h;
}

// ---------------- Wr reorder per layer ----------------
__global__ void reorder_k(const float* __restrict__ rf, const float* __restrict__ rb,
                          int layer) {
    int i = blockIdx.x * 256 + threadIdx.x;
    int k = i / G4;
    int c = i % G4;
    int u = c >> 2, g = c & 3;
    g_wr[layer][0][i] = rf[(size_t)k * G4 + g * U_ + u];
    g_wr[layer][1][i] = rb[(size_t)k * G4 + g * U_ + u];
}

// ---------------- pack B[K][N] -> fp16 fragment order ----------------
__global__ void pack_b_k(const float* __restrict__ in, __half2* __restrict__ out,
                         int K, int N) {
    size_t o = (size_t)blockIdx.x * 256 + threadIdx.x;
    int per_bc = K * 64;
    int bc  = (int)(o / per_bc);
    int rem = (int)(o % per_bc);
    int kt = rem >> 10;
    int r2 = rem & 1023;
    int pg = r2 >> 7;
    int lr = r2 & 127;
    int lane = lr >> 2, r = lr & 3;
    int nt = 2*pg + (r >> 1);
    int breg = r & 1;
    int g = lane >> 2, t4 = lane & 3;
    int k = kt*16 + breg*8 + 2*t4;
    int n = bc*128 + nt*8 + g;
    float v0 = (n < N) ? in[(size_t)k * N + n] : 0.f;
    float v1 = (n < N) ? in[(size_t)(k+1) * N + n] : 0.f;
    out[o] = __floats2half2_rn(v0, v1);
}

// ---------------- fp16 mma GEMM; mode selects row tiling ----------------
// mode 0: rowBase = by*128 (full M)
// mode 1: middle-T rows:  by->(b=by>>1, t0=128+(by&1)*128), rowBase=b*512+t0
// mode 2: outer-T rows:   by->(b=by>>1, t0=(by&1)*384),     rowBase=b*512+t0
__global__ __launch_bounds__(256)
void f16_gemm_k(const __half* __restrict__ Ah, const __half2* __restrict__ Bp,
                const float* __restrict__ bias, float* __restrict__ C,
                int N, int K, int mode)
{
    extern __shared__ __half sm[];
    __half* As = sm;
    uint32_t* Bs = (uint32_t*)(sm + 4*ASTG);

    int tid = threadIdx.x;
    int wid = tid >> 5, lane = tid & 31;
    int wm = wid >> 1, wn = wid & 1;
    int gid = lane >> 2, tg = lane & 3;
    int by = blockIdx.y;
    int rowBase;
    if (mode == 0)      rowBase = by * 128;
    else if (mode == 1) rowBase = (by >> 1)*512 + 128 + (by & 1)*128;
    else                rowBase = (by >> 1)*512 + (by & 1)*384;
    int bc = blockIdx.x;
    int colBase = bc * 128;
    const uint32_t* Bsrc = (const uint32_t*)Bp + (size_t)bc * K * 64;

    float c[2][8][4];
#pragma unroll
    for (int i = 0; i < 2; i++)
#pragma unroll
        for (int j = 0; j < 8; j++)
#pragma unroll
            for (int q = 0; q < 4; q++) c[i][j][q] = 0.f;

    const int nc = K >> 5;

    auto stage = [&](int chunk, int slot) {
#pragma unroll
        for (int it = 0; it < 2; it++) {
            int idx = it * 256 + tid;
            int row = idx >> 2, cq = idx & 3;
            cp16(smem_u32(&As[slot*ASTG + row*40 + cq*8]),
                 Ah + (size_t)(rowBase + row) * K + chunk*32 + cq*8);
            cp16(smem_u32(&Bs[slot*BSTG + idx*4]),
                 Bsrc + (size_t)chunk * BSTG + idx*4);
        }
    };

    stage(0, 0); cp_commit();
    stage(1, 1); cp_commit();

    for (int i = 0; i < nc; i++) {
        if (i + 2 < nc) stage(i + 2, (i + 2) & 3);
        cp_commit();
        cp_wait<2>();
        __syncthreads();

        int slot = i & 3;
        const uint32_t* Au = (const uint32_t*)&As[slot*ASTG];
        const uint32_t* Bu = &Bs[slot*BSTG];
#pragma unroll
        for (int kk = 0; kk < 2; kk++) {
            uint32_t af[2][4];
#pragma unroll
            for (int mt = 0; mt < 2; mt++) {
                int rb = (wm*32 + mt*16 + gid)*20 + kk*8 + tg;
                af[mt][0] = Au[rb];
                af[mt][1] = Au[rb + 160];
                af[mt][2] = Au[rb + 4];
                af[mt][3] = Au[rb + 164];
            }
#pragma unroll
            for (int p = 0; p < 4; p++) {
                uint4 bv = *(const uint4*)&Bu[kk*1024 + ((wn*4 + p)*32 + lane)*4];
                mma_f16(c[0][2*p],   af[0], bv.x, bv.y);
                mma_f16(c[0][2*p+1], af[0], bv.z, bv.w);
                mma_f16(c[1][2*p],   af[1], bv.x, bv.y);
                mma_f16(c[1][2*p+1], af[1], bv.z, bv.w);
            }
        }
    }

#pragma unroll
    for (int mt = 0; mt < 2; mt++) {
        int r0 = rowBase + wm*32 + mt*16 + gid;
#pragma unroll
        for (int nb = 0; nb < 8; nb++) {
            int col = colBase + wn*64 + nb*8 + tg*2;
            if (col < N) {
                float b0 = bias[col], b1 = bias[col + 1];
                *(float2*)&C[(size_t)r0 * N + col] =
                    make_float2(c[mt][nb][0] + b0, c[mt][nb][1] + b1);
                *(float2*)&C[(size_t)(r0 + 8) * N + col] =
                    make_float2(c[mt][nb][2] + b0, c[mt][nb][3] + b1);
            }
        }
    }
}

// ---------------- software grid barrier (64 CTAs per dir) ----------------
__device__ __forceinline__ void grid_barrier(int dir) {
    __syncthreads();
    if (threadIdx.x == 0) {
        __threadfence();
        volatile unsigned* gen = &g_gen[dir];
        unsigned old = *gen;
        unsigned a = atomicAdd(&g_cnt[dir], 1u);
        if (a == 63u) {
            g_cnt[dir] = 0u;
            __threadfence();
            *gen = old + 1u;
        } else {
            while (*gen == old) { }
        }
        __threadfence();
    }
    __syncthreads();
}

// ---------------- persistent bidirectional LSTM, steps [s0, s1) ----------------
// 128 CTAs: dir = bid>>6, ub = bid&63 (8 units). 128 threads = 4 warps.
__global__ __launch_bounds__(128)
void lstm_layer_k(const float* __restrict__ xwf, const float* __restrict__ xwb,
                  const int* __restrict__ tok, __half* __restrict__ y,
                  int layer, int s0, int s1)
{
    extern __shared__ __half smh[];
    uint32_t* swB = (uint32_t*)smh;              // 8192 uint32 = 32 KB B-frags
    __half*   shh = smh + 16384;                 // 32 x HROW halves staged h

    int dir = blockIdx.x >> 6;
    int ub  = blockIdx.x & 63;
    int u0  = ub * 8;
    int tid = threadIdx.x;
    int w   = tid >> 5, lane = tid & 31;
    int gid = lane >> 2, tg = lane & 3;

    const float* xw = dir ? xwb : xwf;
    const float* wr = g_wr[layer][dir];

    // ---- pack Wr slice into B-fragment order ----
    for (int i = tid; i < 8192; i += 128) {
        int r  = i & 1;
        int ln = (i >> 1) & 31;
        int w_ = (i >> 6) & 3;
        int kt = i >> 8;
        int n = w_*8 + (ln >> 2);
        int k = kt*16 + r*8 + 2*(ln & 3);
        __half2 hv = __floats2half2_rn(wr[(size_t)k * G4 + u0*4 + n],
                                       wr[(size_t)(k+1) * G4 + u0*4 + n]);
        swB[i] = *(uint32_t*)&hv;
    }

    int uu = u0 + w*2 + (tg >> 1);
    float cst[4] = {0.f,0.f,0.f,0.f};
    float hst[4] = {0.f,0.f,0.f,0.f};

    if (s0 == 0) {
        for (int i = tid; i < 8*32; i += 128) {
            int bb = i >> 3;
            g_hsh[dir][0][bb * U_ + u0 + (i & 7)] = __float2half_rn(0.f);
        }
    } else {
        const __half* hread0 = g_hsh[dir][s0 & 1];
#pragma unroll
        for (int j = 0; j < 4; j++) {
            int b = (j >> 1)*16 + gid + (j & 1)*8;
            hst[j] = __half2float(hread0[b * U_ + uu]);
            cst[j] = g_cs[dir][b * U_ + uu];
        }
    }

    __threadfence();
    grid_barrier(dir);

    for (int s = s0; s < s1; s++) {
        int t = dir ? (T_ - 1 - s) : s;
        const __half* hread  = g_hsh[dir][s & 1];
        __half*       hwrite = g_hsh[dir][(s & 1) ^ 1];

        // ---- prefetch xw gates + masks ----
        float xwv[2][4];
        int   msk[4];
#pragma unroll
        for (int j = 0; j < 4; j++) {
            int b = (j >> 1)*16 + gid + (j & 1)*8;
            msk[j] = tok[b * T_ + t];
#pragma unroll
            for (int c = 0; c < 2; c++) {
                int col = w*8 + 2*tg + c;
                int gg = col & 3;
                int uc = u0 + (col >> 2);
                xwv[c][j] = xw[((size_t)b * T_ + t) * G4 + gg * U_ + uc];
            }
        }

        // ---- stage h fp16 into SMEM ----
        for (int i = tid; i < 2048; i += 128) {
            int row = i >> 6, ch = i & 63;
            cp16(smem_u32(&shh[row * HROW + ch * 8]),
                 hread + row * U_ + ch * 8);
        }
        cp_commit();
        cp_wait<0>();
        __syncthreads();

        // ---- mma mainloop ----
        float acc[2][4];
#pragma unroll
        for (int mt = 0; mt < 2; mt++)
#pragma unroll
            for (int q = 0; q < 4; q++) acc[mt][q] = 0.f;

        int r8 = lane & 7;
        int quad = lane >> 3;
        uint32_t abase0 = smem_u32(&shh[((quad & 1)*8 + r8) * HROW + (quad >> 1)*8]);
        uint32_t abase1 = abase0 + 16 * HROW * 2;

#pragma unroll 4
        for (int kt = 0; kt < 32; kt++) {
            uint32_t a0[4], a1[4];
            ldmat_x4(a0, abase0 + kt*32);
            ldmat_x4(a1, abase1 + kt*32);
            uint2 bv = *(const uint2*)&swB[(kt*4 + w)*64 + lane*2];
            mma_f16(acc[0], a0, bv.x, bv.y);
            mma_f16(acc[1], a1, bv.x, bv.y);
        }

        // ---- add xw, pair-exchange, cell update ----
        float z[2][4];
#pragma unroll
        for (int mt = 0; mt < 2; mt++)
#pragma unroll
            for (int q = 0; q < 4; q++) {
                int j = mt*2 + (q >> 1);
                z[mt][q] = acc[mt][q] + xwv[q & 1][j];
            }

        float rz[2][4];
#pragma unroll
        for (int mt = 0; mt < 2; mt++)
#pragma unroll
            for (int q = 0; q < 4; q++)
                rz[mt][q] = __shfl_xor_sync(0xffffffffu, z[mt][q], 1);

        if ((tg & 1) == 0) {
#pragma unroll
            for (int j = 0; j < 4; j++) {
                int mt = j >> 1, qr = (j & 1)*2;
                float zi = z [mt][qr], zf = z [mt][qr+1];
                float zg = rz[mt][qr], zo = rz[mt][qr+1];
                float ig = sigf(zi);
                float fg = sigf(zf);
                float gg = tanhfast(zg);
                float og = sigf(zo);
                float cn = fg * cst[j] + ig * gg;
                float hn = og * tanhfast(cn);
                if (msk[j] != 0) { cst[j] = cn; hst[j] = hn; }
                int b = (j >> 1)*16 + gid + (j & 1)*8;
                __half hh = __float2half_rn(hst[j]);
                hwrite[b * U_ + uu] = hh;
                y[((size_t)b * T_ + t) * (2*U_) + dir * U_ + uu] = hh;
            }
        }

        __threadfence();
        grid_barrier(dir);
    }

    // ---- persist c state (even lanes own it) ----
    if ((tg & 1) == 0) {
#pragma unroll
        for (int j = 0; j < 4; j++) {
            int b = (j >> 1)*16 + gid + (j & 1)*8;
            g_cs[dir][b * U_ + uu] = cst[j];
        }
    }
}

// ---------------- streams/events (created at load time) ----------------
static cudaStream_t g_s2;
static cudaEvent_t  g_ev[10];
static struct InitStreams {
    InitStreams() {
        cudaStreamCreateWithFlags(&g_s2, cudaStreamNonBlocking);
        for (int i = 0; i < 10; i++)
            cudaEventCreateWithFlags(&g_ev[i], cudaEventDisableTiming);
    }
} g_initStreams;

// ---------------- host ----------------
extern "C" void kernel_launch(void* const* d_in, const int* in_sizes, int n_in,
                              void* d_out, int out_size)
{
    const int*   tokens = (const int*)  d_in[0];
    const float* emb    = (const float*)d_in[1];
    const float* k1f    = (const float*)d_in[2];
    const float* r1f    = (const float*)d_in[3];
    const float* b1f    = (const float*)d_in[4];
    const float* k1b    = (const float*)d_in[5];
    const float* r1b    = (const float*)d_in[6];
    const float* b1b    = (const float*)d_in[7];
    const float* k2f    = (const float*)d_in[8];
    const float* r2f    = (const float*)d_in[9];
    const float* b2f    = (const float*)d_in[10];
    const float* k2b    = (const float*)d_in[11];
    const float* r2b    = (const float*)d_in[12];
    const float* b2b    = (const float*)d_in[13];
    const float* wd     = (const float*)d_in[14];
    const float* bd     = (const float*)d_in[15];
    float* out = (float*)d_out;

    static __half *pxh = nullptr, *ph1h, *ph2h;
    static float *pxw0, *pxw1;
    static __half2 *pwdP, *pk1P0, *pk1P1, *pk2P0, *pk2P1;
    if (!pxh) {
        cudaGetSymbolAddress((void**)&pxh,  g_xh);
        cudaGetSymbolAddress((void**)&pxw0, g_xw0);
        cudaGetSymbolAddress((void**)&pxw1, g_xw1);
        cudaGetSymbolAddress((void**)&ph1h, g_h1h);
        cudaGetSymbolAddress((void**)&ph2h, g_h2h);
        cudaGetSymbolAddress((void**)&pwdP, g_wdP);
        cudaGetSymbolAddress((void**)&pk1P0, g_k1P);
        pk1P1 = pk1P0 + (size_t)G4 * E_ / 2;
        cudaGetSymbolAddress((void**)&pk2P0, g_k2P);
        pk2P1 = pk2P0 + (size_t)G4 * 2 * U_ / 2;
        cudaFuncSetAttribute(lstm_layer_k,
                             cudaFuncAttributeMaxDynamicSharedMemorySize,
                             32768 + 32*HROW*2);
        cudaFuncSetAttribute(f16_gemm_k,
                             cudaFuncAttributeMaxDynamicSharedMemorySize,
                             4*ASTG*2 + 4*BSTG*4);
    }
    const int lsm = 32768 + 32*HROW*2;
    const int gsm = 4*ASTG*2 + 4*BSTG*4;

    cudaEvent_t EA = g_ev[0], EL1A = g_ev[1], EX2M = g_ev[2];
    cudaEvent_t EL2A = g_ev[3], ELGM = g_ev[4];

    // ---- prep on main stream ----
    embed_k<<<(BT*E_/8)/256, 256>>>(tokens, emb);
    reorder_k<<<(U_*G4)/256, 256>>>(r1f, r1b, 0);
    reorder_k<<<(U_*G4)/256, 256>>>(r2f, r2b, 1);
    pack_b_k<<<(G4*E_/2)/256, 256>>>(k1f, pk1P0, E_, G4);
    pack_b_k<<<(G4*E_/2)/256, 256>>>(k1b, pk1P1, E_, G4);
    cudaEventRecord(EA, 0);

    // ---- s2: remaining weight packs ----
    cudaStreamWaitEvent(g_s2, EA, 0);
    pack_b_k<<<(G4*2*U_/2)/256, 256, 0, g_s2>>>(k2f, pk2P0, 2*U_, G4);
    pack_b_k<<<(G4*2*U_/2)/256, 256, 0, g_s2>>>(k2b, pk2P1, 2*U_, G4);
    pack_b_k<<<((size_t)VPAD*2*U_/2)/256, 256, 0, g_s2>>>(wd, pwdP, 2*U_, V_);

    // ---- main: xW1 full + lstm1 part A ----
    f16_gemm_k<<<dim3(16, 128), 256, gsm>>>(pxh, pk1P0, b1f, pxw0, G4, E_, 0);
    f16_gemm_k<<<dim3(16, 128), 256, gsm>>>(pxh, pk1P1, b1b, pxw1, G4, E_, 0);
    lstm_layer_k<<<128, 128, lsm>>>(pxw0, pxw1, tokens, ph1h, 0, 0, SPLIT);
    cudaEventRecord(EL1A, 0);

    // ---- s2: xW2 middle-T rows (h1 t in [128,384) final) ----
    cudaStreamWaitEvent(g_s2, EL1A, 0);
    f16_gemm_k<<<dim3(16, 64), 256, gsm, g_s2>>>(ph1h, pk2P0, b2f, pxw0, G4, 2*U_, 1);
    f16_gemm_k<<<dim3(16, 64), 256, gsm, g_s2>>>(ph1h, pk2P1, b2b, pxw1, G4, 2*U_, 1);
    cudaEventRecord(EX2M, g_s2);

    // ---- main: lstm1 part B, then xW2 outer-T rows ----
    lstm_layer_k<<<128, 128, lsm>>>(pxw0, pxw1, tokens, ph1h, 0, SPLIT, T_);
    f16_gemm_k<<<dim3(16, 64), 256, gsm>>>(ph1h, pk2P0, b2f, pxw0, G4, 2*U_, 2);
    f16_gemm_k<<<dim3(16, 64), 256, gsm>>>(ph1h, pk2P1, b2b, pxw1, G4, 2*U_, 2);
    cudaStreamWaitEvent(0, EX2M, 0);

    // ---- main: lstm2 part A ----
    lstm_layer_k<<<128, 128, lsm>>>(pxw0, pxw1, tokens, ph2h, 1, 0, SPLIT);
    cudaEventRecord(EL2A, 0);

    // ---- s2: logits middle-T rows ----
    cudaStreamWaitEvent(g_s2, EL2A, 0);
    f16_gemm_k<<<dim3(63, 64), 256, gsm, g_s2>>>(ph2h, pwdP, bd, out, V_, 2*U_, 1);
    cudaEventRecord(ELGM, g_s2);

    // ---- main: lstm2 part B, logits outer-T rows, join ----
    lstm_layer_k<<<128, 128, lsm>>>(pxw0, pxw1, tokens, ph2h, 1, SPLIT, T_);
    f16_gemm_k<<<dim3(63, 64), 256, gsm>>>(ph2h, pwdP, bd, out, V_, 2*U_, 2);
    cudaStreamWaitEvent(0, ELGM, 0);
}

// round 14
// speedup vs baseline: 2.0031x; 1.0671x over previous
#include <cuda_runtime.h>
#include <cuda_fp16.h>
#include <math.h>
#include <stdint.h>

#define B_ 32
#define T_ 512
#define V_ 8000
#define E_ 256
#define U_ 512
#define G4 (4*U_)     // 2048
#define BT (B_*T_)    // 16384
#define VPAD 8064
#define SPLIT 384

#define ASTG 5120
#define BSTG 2048
#define HROW 520

// ---------------- static device scratch ----------------
__device__ __half g_xh [BT*E_];
__device__ float  g_xw0[(size_t)BT*G4];
__device__ float  g_xw1[(size_t)BT*G4];
__device__ __half g_h1h[(size_t)BT*2*U_];
__device__ __half g_h2h[(size_t)BT*2*U_];
__device__ float  g_wr [2][2][U_*G4];            // [layer][dir]
__device__ __half g_hsh[2][2][B_*U_];            // [dir][parity]
__device__ float  g_cs [2][B_*U_];               // persisted c state [dir]
__device__ __half2 g_wdP[(size_t)VPAD*2*U_/2];
__device__ __half2 g_k1P[2][(size_t)G4*E_/2];
__device__ __half2 g_k2P[2][(size_t)G4*2*U_/2];
__device__ unsigned g_gen[2];
__device__ unsigned g_cnt[2];

// ---------------- helpers ----------------
__device__ __forceinline__ uint32_t smem_u32(const void* p) {
    uint32_t a;
    asm("{ .reg .u64 t; cvta.to.shared.u64 t, %1; cvt.u32.u64 %0, t; }" : "=r"(a) : "l"(p));
    return a;
}
__device__ __forceinline__ void cp16(uint32_t dst, const void* src) {
    asm volatile("cp.async.ca.shared.global [%0], [%1], 16;" :: "r"(dst), "l"(src));
}
__device__ __forceinline__ void cp_commit() {
    asm volatile("cp.async.commit_group;" ::: "memory");
}
template <int N>
__device__ __forceinline__ void cp_wait() {
    asm volatile("cp.async.wait_group %0;" :: "n"(N) : "memory");
}
__device__ __forceinline__ void mma_f16(float c[4], const uint32_t a[4], uint32_t b0, uint32_t b1) {
    asm volatile(
        "mma.sync.aligned.m16n8k16.row.col.f32.f16.f16.f32 "
        "{%0,%1,%2,%3}, {%4,%5,%6,%7}, {%8,%9}, {%0,%1,%2,%3};"
        : "+f"(c[0]), "+f"(c[1]), "+f"(c[2]), "+f"(c[3])
        : "r"(a[0]), "r"(a[1]), "r"(a[2]), "r"(a[3]), "r"(b0), "r"(b1));
}
__device__ __forceinline__ void ldmat_x4(uint32_t r[4], uint32_t addr) {
    asm volatile("ldmatrix.sync.aligned.m8n8.x4.shared.b16 {%0,%1,%2,%3}, [%4];"
                 : "=r"(r[0]), "=r"(r[1]), "=r"(r[2]), "=r"(r[3]) : "r"(addr));
}
__device__ __forceinline__ float sigf(float x) {
    return __fdividef(1.f, 1.f + __expf(-x));
}
__device__ __forceinline__ float tanhfast(float x) {
    return fmaf(2.f, sigf(2.f * x), -1.f);
}

// ---------------- embedding gather -> fp16 ----------------
__global__ void embed_k(const int* __restrict__ tok, const float* __restrict__ emb) {
    int i = blockIdx.x * 256 + threadIdx.x;
    int row = i >> 5;
    int c8  = i & 31;
    int t = tok[row];
    const float4* s = (const float4*)(emb + (size_t)t * E_ + c8 * 8);
    float4 v0 = s[0], v1 = s[1];
    __half2 h[4];
    h[0] = __floats2half2_rn(v0.x, v0.y);
    h[1] = __floats2half2_rn(v0.z, v0.w);
    h[2] = __floats2half2_rn(v1.x, v1.y);
    h[3] = __floats2half2_rn(v1.z, v1.w);
    *(uint4*)&g_xh[(size_t)row * E_ + c8 * 8] = *(uint4*)h;
}

// ---------------- Wr reorder per layer ----------------
__global__ void reorder_k(const float* __restrict__ rf, const float* __restrict__ rb,
                          int layer) {
    int i = blockIdx.x * 256 + threadIdx.x;
    int k = i / G4;
    int c = i % G4;
    int u = c >> 2, g = c & 3;
    g_wr[layer][0][i] = rf[(size_t)k * G4 + g * U_ + u];
    g_wr[layer][1][i] = rb[(size_t)k * G4 + g * U_ + u];
}

// ---------------- pack B[K][N] -> fp16 fragment order ----------------
__global__ void pack_b_k(const float* __restrict__ in, __half2* __restrict__ out,
                         int K, int N) {
    size_t o = (size_t)blockIdx.x * 256 + threadIdx.x;
    int per_bc = K * 64;
    int bc  = (int)(o / per_bc);
    int rem = (int)(o % per_bc);
    int kt = rem >> 10;
    int r2 = rem & 1023;
    int pg = r2 >> 7;
    int lr = r2 & 127;
    int lane = lr >> 2, r = lr & 3;
    int nt = 2*pg + (r >> 1);
    int breg = r & 1;
    int g = lane >> 2, t4 = lane & 3;
    int k = kt*16 + breg*8 + 2*t4;
    int n = bc*128 + nt*8 + g;
    float v0 = (n < N) ? in[(size_t)k * N + n] : 0.f;
    float v1 = (n < N) ? in[(size_t)(k+1) * N + n] : 0.f;
    out[o] = __floats2half2_rn(v0, v1);
}

// ---------------- fp16 mma GEMM; mode selects row tiling ----------------
// mode 0: rowBase = by*128
// mode 1: middle-T rows [128,384): rowBase = (by>>1)*512 + 128 + (by&1)*128
// mode 2: outer-T rows [0,128)+[384,512): rowBase = (by>>1)*512 + (by&1)*384
__global__ __launch_bounds__(256)
void f16_gemm_k(const __half* __restrict__ Ah, const __half2* __restrict__ Bp,
                const float* __restrict__ bias, float* __restrict__ C,
                int N, int K, int mode)
{
    extern __shared__ __half sm[];
    __half* As = sm;
    uint32_t* Bs = (uint32_t*)(sm + 4*ASTG);

    int tid = threadIdx.x;
    int wid = tid >> 5, lane = tid & 31;
    int wm = wid >> 1, wn = wid & 1;
    int gid = lane >> 2, tg = lane & 3;
    int by = blockIdx.y;
    int rowBase;
    if (mode == 0)      rowBase = by * 128;
    else if (mode == 1) rowBase = (by >> 1)*512 + 128 + (by & 1)*128;
    else                rowBase = (by >> 1)*512 + (by & 1)*384;
    int bc = blockIdx.x;
    int colBase = bc * 128;
    const uint32_t* Bsrc = (const uint32_t*)Bp + (size_t)bc * K * 64;

    float c[2][8][4];
#pragma unroll
    for (int i = 0; i < 2; i++)
#pragma unroll
        for (int j = 0; j < 8; j++)
#pragma unroll
            for (int q = 0; q < 4; q++) c[i][j][q] = 0.f;

    const int nc = K >> 5;

    auto stage = [&](int chunk, int slot) {
#pragma unroll
        for (int it = 0; it < 2; it++) {
            int idx = it * 256 + tid;
            int row = idx >> 2, cq = idx & 3;
            cp16(smem_u32(&As[slot*ASTG + row*40 + cq*8]),
                 Ah + (size_t)(rowBase + row) * K + chunk*32 + cq*8);
            cp16(smem_u32(&Bs[slot*BSTG + idx*4]),
                 Bsrc + (size_t)chunk * BSTG + idx*4);
        }
    };

    stage(0, 0); cp_commit();
    stage(1, 1); cp_commit();

    for (int i = 0; i < nc; i++) {
        if (i + 2 < nc) stage(i + 2, (i + 2) & 3);
        cp_commit();
        cp_wait<2>();
        __syncthreads();

        int slot = i & 3;
        const uint32_t* Au = (const uint32_t*)&As[slot*ASTG];
        const uint32_t* Bu = &Bs[slot*BSTG];
#pragma unroll
        for (int kk = 0; kk < 2; kk++) {
            uint32_t af[2][4];
#pragma unroll
            for (int mt = 0; mt < 2; mt++) {
                int rb = (wm*32 + mt*16 + gid)*20 + kk*8 + tg;
                af[mt][0] = Au[rb];
                af[mt][1] = Au[rb + 160];
                af[mt][2] = Au[rb + 4];
                af[mt][3] = Au[rb + 164];
            }
#pragma unroll
            for (int p = 0; p < 4; p++) {
                uint4 bv = *(const uint4*)&Bu[kk*1024 + ((wn*4 + p)*32 + lane)*4];
                mma_f16(c[0][2*p],   af[0], bv.x, bv.y);
                mma_f16(c[0][2*p+1], af[0], bv.z, bv.w);
                mma_f16(c[1][2*p],   af[1], bv.x, bv.y);
                mma_f16(c[1][2*p+1], af[1], bv.z, bv.w);
            }
        }
    }

#pragma unroll
    for (int mt = 0; mt < 2; mt++) {
        int r0 = rowBase + wm*32 + mt*16 + gid;
#pragma unroll
        for (int nb = 0; nb < 8; nb++) {
            int col = colBase + wn*64 + nb*8 + tg*2;
            if (col < N) {
                float b0 = bias[col], b1 = bias[col + 1];
                *(float2*)&C[(size_t)r0 * N + col] =
                    make_float2(c[mt][nb][0] + b0, c[mt][nb][1] + b1);
                *(float2*)&C[(size_t)(r0 + 8) * N + col] =
                    make_float2(c[mt][nb][2] + b0, c[mt][nb][3] + b1);
            }
        }
    }
}

// ---------------- software grid barrier (release/acquire, no membar) ----------------
__device__ __forceinline__ void grid_barrier(int dir) {
    __syncthreads();
    if (threadIdx.x == 0) {
        unsigned* genp = &g_gen[dir];
        unsigned* cntp = &g_cnt[dir];
        unsigned old;
        asm volatile("ld.relaxed.gpu.u32 %0, [%1];" : "=r"(old) : "l"(genp) : "memory");
        unsigned a;
        asm volatile("atom.add.acq_rel.gpu.u32 %0, [%1], 1;" : "=r"(a) : "l"(cntp) : "memory");
        if (a == 63u) {
            asm volatile("st.relaxed.gpu.u32 [%0], 0;" :: "l"(cntp) : "memory");
            asm volatile("st.release.gpu.u32 [%0], %1;" :: "l"(genp), "r"(old + 1u) : "memory");
        } else {
            unsigned g;
            do {
                asm volatile("ld.acquire.gpu.u32 %0, [%1];" : "=r"(g) : "l"(genp) : "memory");
            } while (g == old);
        }
    }
    __syncthreads();
}

// ---------------- persistent bidirectional LSTM, steps [s0, s1) ----------------
__global__ __launch_bounds__(128)
void lstm_layer_k(const float* __restrict__ xwf, const float* __restrict__ xwb,
                  const int* __restrict__ tok, __half* __restrict__ y,
                  int layer, int s0, int s1)
{
    extern __shared__ __half smh[];
    uint32_t* swB = (uint32_t*)smh;              // 32 KB B-frags
    __half*   shh = smh + 16384;                 // 32 x HROW halves

    int dir = blockIdx.x >> 6;
    int ub  = blockIdx.x & 63;
    int u0  = ub * 8;
    int tid = threadIdx.x;
    int w   = tid >> 5, lane = tid & 31;
    int gid = lane >> 2, tg = lane & 3;

    const float* xw = dir ? xwb : xwf;
    const float* wr = g_wr[layer][dir];

    // ---- pack Wr slice into B-fragment order ----
    for (int i = tid; i < 8192; i += 128) {
        int r  = i & 1;
        int ln = (i >> 1) & 31;
        int w_ = (i >> 6) & 3;
        int kt = i >> 8;
        int n = w_*8 + (ln >> 2);
        int k = kt*16 + r*8 + 2*(ln & 3);
        __half2 hv = __floats2half2_rn(wr[(size_t)k * G4 + u0*4 + n],
                                       wr[(size_t)(k+1) * G4 + u0*4 + n]);
        swB[i] = *(uint32_t*)&hv;
    }

    int uu = u0 + w*2 + (tg >> 1);
    float cst[4] = {0.f,0.f,0.f,0.f};
    float hst[4] = {0.f,0.f,0.f,0.f};

    if (s0 == 0) {
        for (int i = tid; i < 8*32; i += 128) {
            int bb = i >> 3;
            g_hsh[dir][0][bb * U_ + u0 + (i & 7)] = __float2half_rn(0.f);
        }
    } else {
        const __half* hread0 = g_hsh[dir][s0 & 1];
#pragma unroll
        for (int j = 0; j < 4; j++) {
            int b = (j >> 1)*16 + gid + (j & 1)*8;
            hst[j] = __half2float(hread0[b * U_ + uu]);
            cst[j] = g_cs[dir][b * U_ + uu];
        }
    }

    grid_barrier(dir);

    for (int s = s0; s < s1; s++) {
        int t = dir ? (T_ - 1 - s) : s;
        const __half* hread  = g_hsh[dir][s & 1];
        __half*       hwrite = g_hsh[dir][(s & 1) ^ 1];

        // ---- prefetch xw gates + masks ----
        float xwv[2][4];
        int   msk[4];
#pragma unroll
        for (int j = 0; j < 4; j++) {
            int b = (j >> 1)*16 + gid + (j & 1)*8;
            msk[j] = tok[b * T_ + t];
#pragma unroll
            for (int c = 0; c < 2; c++) {
                int col = w*8 + 2*tg + c;
                int gg = col & 3;
                int uc = u0 + (col >> 2);
                xwv[c][j] = xw[((size_t)b * T_ + t) * G4 + gg * U_ + uc];
            }
        }

        // ---- stage h fp16 into SMEM, two halves ----
        for (int i = tid; i < 1024; i += 128) {
            int row = i >> 5, ch = i & 31;
            cp16(smem_u32(&shh[row * HROW + ch * 8]),
                 hread + row * U_ + ch * 8);
        }
        cp_commit();
        for (int i = tid; i < 1024; i += 128) {
            int row = i >> 5, ch = (i & 31) + 32;
            cp16(smem_u32(&shh[row * HROW + ch * 8]),
                 hread + row * U_ + ch * 8);
        }
        cp_commit();
        cp_wait<1>();
        __syncthreads();

        // ---- mma mainloop (first k half while second stages) ----
        float acc[2][4];
#pragma unroll
        for (int mt = 0; mt < 2; mt++)
#pragma unroll
            for (int q = 0; q < 4; q++) acc[mt][q] = 0.f;

        int r8 = lane & 7;
        int quad = lane >> 3;
        uint32_t abase0 = smem_u32(&shh[((quad & 1)*8 + r8) * HROW + (quad >> 1)*8]);
        uint32_t abase1 = abase0 + 16 * HROW * 2;

#pragma unroll 4
        for (int kt = 0; kt < 16; kt++) {
            uint32_t a0[4], a1[4];
            ldmat_x4(a0, abase0 + kt*32);
            ldmat_x4(a1, abase1 + kt*32);
            uint2 bv = *(const uint2*)&swB[(kt*4 + w)*64 + lane*2];
            mma_f16(acc[0], a0, bv.x, bv.y);
            mma_f16(acc[1], a1, bv.x, bv.y);
        }
        cp_wait<0>();
        __syncthreads();
#pragma unroll 4
        for (int kt = 16; kt < 32; kt++) {
            uint32_t a0[4], a1[4];
            ldmat_x4(a0, abase0 + kt*32);
            ldmat_x4(a1, abase1 + kt*32);
            uint2 bv = *(const uint2*)&swB[(kt*4 + w)*64 + lane*2];
            mma_f16(acc[0], a0, bv.x, bv.y);
            mma_f16(acc[1], a1, bv.x, bv.y);
        }

        // ---- add xw, pair-exchange (i,f)/(g,o), cell update ----
        float z[2][4];
#pragma unroll
        for (int mt = 0; mt < 2; mt++)
#pragma unroll
            for (int q = 0; q < 4; q++) {
                int j = mt*2 + (q >> 1);
                z[mt][q] = acc[mt][q] + xwv[q & 1][j];
            }

        float rz[2][4];
#pragma unroll
        for (int mt = 0; mt < 2; mt++)
#pragma unroll
            for (int q = 0; q < 4; q++)
                rz[mt][q] = __shfl_xor_sync(0xffffffffu, z[mt][q], 1);

        if ((tg & 1) == 0) {
#pragma unroll
            for (int j = 0; j < 4; j++) {
                int mt = j >> 1, qr = (j & 1)*2;
                float zi = z [mt][qr], zf = z [mt][qr+1];
                float zg = rz[mt][qr], zo = rz[mt][qr+1];
                float ig = sigf(zi);
                float fg = sigf(zf);
                float gg = tanhfast(zg);
                float og = sigf(zo);
                float cn = fg * cst[j] + ig * gg;
                float hn = og * tanhfast(cn);
                if (msk[j] != 0) { cst[j] = cn; hst[j] = hn; }
            }
        }

        // ---- packed half2 stores: tg=0 lane stores units (uu, uu+1) ----
#pragma unroll
        for (int j = 0; j < 4; j++) {
            float oth = __shfl_xor_sync(0xffffffffu, hst[j], 2);
            if (tg == 0) {
                int b = (j >> 1)*16 + gid + (j & 1)*8;
                __half2 hp = __floats2half2_rn(hst[j], oth);
                *(__half2*)&hwrite[b * U_ + uu] = hp;
                *(__half2*)&y[((size_t)b * T_ + t) * (2*U_) + dir * U_ + uu] = hp;
            }
        }

        grid_barrier(dir);
    }

    // ---- persist c state ----
    if ((tg & 1) == 0) {
#pragma unroll
        for (int j = 0; j < 4; j++) {
            int b = (j >> 1)*16 + gid + (j & 1)*8;
            g_cs[dir][b * U_ + uu] = cst[j];
        }
    }
}

// ---------------- streams/events (created at load time) ----------------
static cudaStream_t g_s2;
static cudaEvent_t  g_ev[10];
static struct InitStreams {
    InitStreams() {
        cudaStreamCreateWithFlags(&g_s2, cudaStreamNonBlocking);
        for (int i = 0; i < 10; i++)
            cudaEventCreateWithFlags(&g_ev[i], cudaEventDisableTiming);
    }
} g_initStreams;

// ---------------- host ----------------
extern "C" void kernel_launch(void* const* d_in, const int* in_sizes, int n_in,
                              void* d_out, int out_size)
{
    const int*   tokens = (const int*)  d_in[0];
    const float* emb    = (const float*)d_in[1];
    const float* k1f    = (const float*)d_in[2];
    const float* r1f    = (const float*)d_in[3];
    const float* b1f    = (const float*)d_in[4];
    const float* k1b    = (const float*)d_in[5];
    const float* r1b    = (const float*)d_in[6];
    const float* b1b    = (const float*)d_in[7];
    const float* k2f    = (const float*)d_in[8];
    const float* r2f    = (const float*)d_in[9];
    const float* b2f    = (const float*)d_in[10];
    const float* k2b    = (const float*)d_in[11];
    const float* r2b    = (const float*)d_in[12];
    const float* b2b    = (const float*)d_in[13];
    const float* wd     = (const float*)d_in[14];
    const float* bd     = (const float*)d_in[15];
    float* out = (float*)d_out;

    static __half *pxh = nullptr, *ph1h, *ph2h;
    static float *pxw0, *pxw1;
    static __half2 *pwdP, *pk1P0, *pk1P1, *pk2P0, *pk2P1;
    if (!pxh) {
        cudaGetSymbolAddress((void**)&pxh,  g_xh);
        cudaGetSymbolAddress((void**)&pxw0, g_xw0);
        cudaGetSymbolAddress((void**)&pxw1, g_xw1);
        cudaGetSymbolAddress((void**)&ph1h, g_h1h);
        cudaGetSymbolAddress((void**)&ph2h, g_h2h);
        cudaGetSymbolAddress((void**)&pwdP, g_wdP);
        cudaGetSymbolAddress((void**)&pk1P0, g_k1P);
        pk1P1 = pk1P0 + (size_t)G4 * E_ / 2;
        cudaGetSymbolAddress((void**)&pk2P0, g_k2P);
        pk2P1 = pk2P0 + (size_t)G4 * 2 * U_ / 2;
        cudaFuncSetAttribute(lstm_layer_k,
                             cudaFuncAttributeMaxDynamicSharedMemorySize,
                             32768 + 32*HROW*2);
        cudaFuncSetAttribute(f16_gemm_k,
                             cudaFuncAttributeMaxDynamicSharedMemorySize,
                             4*ASTG*2 + 4*BSTG*4);
    }
    const int lsm = 32768 + 32*HROW*2;
    const int gsm = 4*ASTG*2 + 4*BSTG*4;

    cudaEvent_t EA = g_ev[0], EX1M = g_ev[1], EPK = g_ev[2];
    cudaEvent_t EL1A = g_ev[3], EX2M = g_ev[4], EL2A = g_ev[5], ELGM = g_ev[6];

    // ---- prep on main stream ----
    embed_k<<<(BT*E_/8)/256, 256>>>(tokens, emb);
    reorder_k<<<(U_*G4)/256, 256>>>(r1f, r1b, 0);
    reorder_k<<<(U_*G4)/256, 256>>>(r2f, r2b, 1);
    pack_b_k<<<(G4*E_/2)/256, 256>>>(k1f, pk1P0, E_, G4);
    pack_b_k<<<(G4*E_/2)/256, 256>>>(k1b, pk1P1, E_, G4);
    cudaEventRecord(EA, 0);

    // ---- s2: xW1 middle-T, then remaining packs ----
    cudaStreamWaitEvent(g_s2, EA, 0);
    f16_gemm_k<<<dim3(16, 64), 256, gsm, g_s2>>>(pxh, pk1P0, b1f, pxw0, G4, E_, 1);
    f16_gemm_k<<<dim3(16, 64), 256, gsm, g_s2>>>(pxh, pk1P1, b1b, pxw1, G4, E_, 1);
    cudaEventRecord(EX1M, g_s2);
    pack_b_k<<<(G4*2*U_/2)/256, 256, 0, g_s2>>>(k2f, pk2P0, 2*U_, G4);
    pack_b_k<<<(G4*2*U_/2)/256, 256, 0, g_s2>>>(k2b, pk2P1, 2*U_, G4);
    pack_b_k<<<((size_t)VPAD*2*U_/2)/256, 256, 0, g_s2>>>(wd, pwdP, 2*U_, V_);
    cudaEventRecord(EPK, g_s2);

    // ---- main: xW1 outer-T + lstm1 [0,128) ----
    f16_gemm_k<<<dim3(16, 64), 256, gsm>>>(pxh, pk1P0, b1f, pxw0, G4, E_, 2);
    f16_gemm_k<<<dim3(16, 64), 256, gsm>>>(pxh, pk1P1, b1b, pxw1, G4, E_, 2);
    lstm_layer_k<<<128, 128, lsm>>>(pxw0, pxw1, tokens, ph1h, 0, 0, 128);
    cudaStreamWaitEvent(0, EX1M, 0);
    lstm_layer_k<<<128, 128, lsm>>>(pxw0, pxw1, tokens, ph1h, 0, 128, SPLIT);
    cudaEventRecord(EL1A, 0);

    // ---- s2: xW2 middle-T (h1 t in [128,384) final) ----
    cudaStreamWaitEvent(g_s2, EL1A, 0);
    f16_gemm_k<<<dim3(16, 64), 256, gsm, g_s2>>>(ph1h, pk2P0, b2f, pxw0, G4, 2*U_, 1);
    f16_gemm_k<<<dim3(16, 64), 256, gsm, g_s2>>>(ph1h, pk2P1, b2b, pxw1, G4, 2*U_, 1);
    cudaEventRecord(EX2M, g_s2);

    // ---- main: lstm1 part B, xW2 outer-T, lstm2 part A ----
    lstm_layer_k<<<128, 128, lsm>>>(pxw0, pxw1, tokens, ph1h, 0, SPLIT, T_);
    cudaStreamWaitEvent(0, EPK, 0);
    f16_gemm_k<<<dim3(16, 64), 256, gsm>>>(ph1h, pk2P0, b2f, pxw0, G4, 2*U_, 2);
    f16_gemm_k<<<dim3(16, 64), 256, gsm>>>(ph1h, pk2P1, b2b, pxw1, G4, 2*U_, 2);
    cudaStreamWaitEvent(0, EX2M, 0);
    lstm_layer_k<<<128, 128, lsm>>>(pxw0, pxw1, tokens, ph2h, 1, 0, SPLIT);
    cudaEventRecord(EL2A, 0);

    // ---- s2: logits middle-T ----
    cudaStreamWaitEvent(g_s2, EL2A, 0);
    f16_gemm_k<<<dim3(63, 64), 256, gsm, g_s2>>>(ph2h, pwdP, bd, out, V_, 2*U_, 1);
    cudaEventRecord(ELGM, g_s2);

    // ---- main: lstm2 part B, logits outer-T, join ----
    lstm_layer_k<<<128, 128, lsm>>>(pxw0, pxw1, tokens, ph2h, 1, SPLIT, T_);
    f16_gemm_k<<<dim3(63, 64), 256, gsm>>>(ph2h, pwdP, bd, out, V_, 2*U_, 2);
    cudaStreamWaitEvent(0, ELGM, 0);
}

// round 15
// speedup vs baseline: 2.0428x; 1.0198x over previous
#include <cuda_runtime.h>
#include <cuda_fp16.h>
#include <math.h>
#include <stdint.h>

#define B_ 32
#define T_ 512
#define V_ 8000
#define E_ 256
#define U_ 512
#define G4 (4*U_)     // 2048
#define BT (B_*T_)    // 16384
#define VPAD 8064
#define SPLIT 384

#define ASTG 5120
#define BSTG 2048
#define HROW 520

// ---------------- static device scratch ----------------
__device__ __half g_xh [BT*E_];
__device__ float  g_xw0[(size_t)BT*G4];
__device__ float  g_xw1[(size_t)BT*G4];
__device__ __half g_h1h[(size_t)BT*2*U_];
__device__ __half g_h2h[(size_t)BT*2*U_];
__device__ float  g_wr [2][2][U_*G4];            // [layer][dir]
__device__ __half g_hsh[2][2][B_*U_];            // [dir][parity]
__device__ float  g_cs [2][B_*U_];               // persisted c state [dir]
__device__ __half2 g_wdP[(size_t)VPAD*2*U_/2];
__device__ __half2 g_k1P[2][(size_t)G4*E_/2];
__device__ __half2 g_k2P[2][(size_t)G4*2*U_/2];
__device__ unsigned g_gen[2];
__device__ unsigned g_cnt[2];

// ---------------- helpers ----------------
__device__ __forceinline__ uint32_t smem_u32(const void* p) {
    uint32_t a;
    asm("{ .reg .u64 t; cvta.to.shared.u64 t, %1; cvt.u32.u64 %0, t; }" : "=r"(a) : "l"(p));
    return a;
}
__device__ __forceinline__ void cp16(uint32_t dst, const void* src) {
    asm volatile("cp.async.ca.shared.global [%0], [%1], 16;" :: "r"(dst), "l"(src));
}
__device__ __forceinline__ void cp_commit() {
    asm volatile("cp.async.commit_group;" ::: "memory");
}
template <int N>
__device__ __forceinline__ void cp_wait() {
    asm volatile("cp.async.wait_group %0;" :: "n"(N) : "memory");
}
__device__ __forceinline__ void mma_f16(float c[4], const uint32_t a[4], uint32_t b0, uint32_t b1) {
    asm volatile(
        "mma.sync.aligned.m16n8k16.row.col.f32.f16.f16.f32 "
        "{%0,%1,%2,%3}, {%4,%5,%6,%7}, {%8,%9}, {%0,%1,%2,%3};"
        : "+f"(c[0]), "+f"(c[1]), "+f"(c[2]), "+f"(c[3])
        : "r"(a[0]), "r"(a[1]), "r"(a[2]), "r"(a[3]), "r"(b0), "r"(b1));
}
__device__ __forceinline__ void ldmat_x4(uint32_t r[4], uint32_t addr) {
    asm volatile("ldmatrix.sync.aligned.m8n8.x4.shared.b16 {%0,%1,%2,%3}, [%4];"
                 : "=r"(r[0]), "=r"(r[1]), "=r"(r[2]), "=r"(r[3]) : "r"(addr));
}
__device__ __forceinline__ float sigf(float x) {
    return __fdividef(1.f, 1.f + __expf(-x));
}
__device__ __forceinline__ float tanhfast(float x) {
    return fmaf(2.f, sigf(2.f * x), -1.f);
}

// ---------------- embedding gather -> fp16 ----------------
__global__ void embed_k(const int* __restrict__ tok, const float* __restrict__ emb) {
    int i = blockIdx.x * 256 + threadIdx.x;
    int row = i >> 5;
    int c8  = i & 31;
    int t = tok[row];
    const float4* s = (const float4*)(emb + (size_t)t * E_ + c8 * 8);
    float4 v0 = s[0], v1 = s[1];
    __half2 h[4];
    h[0] = __floats2half2_rn(v0.x, v0.y);
    h[1] = __floats2half2_rn(v0.z, v0.w);
    h[2] = __floats2half2_rn(v1.x, v1.y);
    h[3] = __floats2half2_rn(v1.z, v1.w);
    *(uint4*)&g_xh[(size_t)row * E_ + c8 * 8] = *(uint4*)h;
}

// ---------------- Wr reorder per layer ----------------
__global__ void reorder_k(const float* __restrict__ rf, const float* __restrict__ rb,
                          int layer) {
    int i = blockIdx.x * 256 + threadIdx.x;
    int k = i / G4;
    int c = i % G4;
    int u = c >> 2, g = c & 3;
    g_wr[layer][0][i] = rf[(size_t)k * G4 + g * U_ + u];
    g_wr[layer][1][i] = rb[(size_t)k * G4 + g * U_ + u];
}

// ---------------- pack B[K][N] -> fp16 fragment order ----------------
__global__ void pack_b_k(const float* __restrict__ in, __half2* __restrict__ out,
                         int K, int N) {
    size_t o = (size_t)blockIdx.x * 256 + threadIdx.x;
    int per_bc = K * 64;
    int bc  = (int)(o / per_bc);
    int rem = (int)(o % per_bc);
    int kt = rem >> 10;
    int r2 = rem & 1023;
    int pg = r2 >> 7;
    int lr = r2 & 127;
    int lane = lr >> 2, r = lr & 3;
    int nt = 2*pg + (r >> 1);
    int breg = r & 1;
    int g = lane >> 2, t4 = lane & 3;
    int k = kt*16 + breg*8 + 2*t4;
    int n = bc*128 + nt*8 + g;
    float v0 = (n < N) ? in[(size_t)k * N + n] : 0.f;
    float v1 = (n < N) ? in[(size_t)(k+1) * N + n] : 0.f;
    out[o] = __floats2half2_rn(v0, v1);
}

// ---------------- fp16 mma GEMM; mode selects row tiling ----------------
__global__ __launch_bounds__(256)
void f16_gemm_k(const __half* __restrict__ Ah, const __half2* __restrict__ Bp,
                const float* __restrict__ bias, float* __restrict__ C,
                int N, int K, int mode)
{
    extern __shared__ __half sm[];
    __half* As = sm;
    uint32_t* Bs = (uint32_t*)(sm + 4*ASTG);

    int tid = threadIdx.x;
    int wid = tid >> 5, lane = tid & 31;
    int wm = wid >> 1, wn = wid & 1;
    int gid = lane >> 2, tg = lane & 3;
    int by = blockIdx.y;
    int rowBase;
    if (mode == 0)      rowBase = by * 128;
    else if (mode == 1) rowBase = (by >> 1)*512 + 128 + (by & 1)*128;
    else                rowBase = (by >> 1)*512 + (by & 1)*384;
    int bc = blockIdx.x;
    int colBase = bc * 128;
    const uint32_t* Bsrc = (const uint32_t*)Bp + (size_t)bc * K * 64;

    float c[2][8][4];
#pragma unroll
    for (int i = 0; i < 2; i++)
#pragma unroll
        for (int j = 0; j < 8; j++)
#pragma unroll
            for (int q = 0; q < 4; q++) c[i][j][q] = 0.f;

    const int nc = K >> 5;

    auto stage = [&](int chunk, int slot) {
#pragma unroll
        for (int it = 0; it < 2; it++) {
            int idx = it * 256 + tid;
            int row = idx >> 2, cq = idx & 3;
            cp16(smem_u32(&As[slot*ASTG + row*40 + cq*8]),
                 Ah + (size_t)(rowBase + row) * K + chunk*32 + cq*8);
            cp16(smem_u32(&Bs[slot*BSTG + idx*4]),
                 Bsrc + (size_t)chunk * BSTG + idx*4);
        }
    };

    stage(0, 0); cp_commit();
    stage(1, 1); cp_commit();

    for (int i = 0; i < nc; i++) {
        if (i + 2 < nc) stage(i + 2, (i + 2) & 3);
        cp_commit();
        cp_wait<2>();
        __syncthreads();

        int slot = i & 3;
        const uint32_t* Au = (const uint32_t*)&As[slot*ASTG];
        const uint32_t* Bu = &Bs[slot*BSTG];
#pragma unroll
        for (int kk = 0; kk < 2; kk++) {
            uint32_t af[2][4];
#pragma unroll
            for (int mt = 0; mt < 2; mt++) {
                int rb = (wm*32 + mt*16 + gid)*20 + kk*8 + tg;
                af[mt][0] = Au[rb];
                af[mt][1] = Au[rb + 160];
                af[mt][2] = Au[rb + 4];
                af[mt][3] = Au[rb + 164];
            }
#pragma unroll
            for (int p = 0; p < 4; p++) {
                uint4 bv = *(const uint4*)&Bu[kk*1024 + ((wn*4 + p)*32 + lane)*4];
                mma_f16(c[0][2*p],   af[0], bv.x, bv.y);
                mma_f16(c[0][2*p+1], af[0], bv.z, bv.w);
                mma_f16(c[1][2*p],   af[1], bv.x, bv.y);
                mma_f16(c[1][2*p+1], af[1], bv.z, bv.w);
            }
        }
    }

#pragma unroll
    for (int mt = 0; mt < 2; mt++) {
        int r0 = rowBase + wm*32 + mt*16 + gid;
#pragma unroll
        for (int nb = 0; nb < 8; nb++) {
            int col = colBase + wn*64 + nb*8 + tg*2;
            if (col < N) {
                float b0 = bias[col], b1 = bias[col + 1];
                *(float2*)&C[(size_t)r0 * N + col] =
                    make_float2(c[mt][nb][0] + b0, c[mt][nb][1] + b1);
                *(float2*)&C[(size_t)(r0 + 8) * N + col] =
                    make_float2(c[mt][nb][2] + b0, c[mt][nb][3] + b1);
            }
        }
    }
}

// ---------------- software grid barrier (release/acquire) ----------------
__device__ __forceinline__ void grid_barrier(int dir) {
    __syncthreads();
    if (threadIdx.x == 0) {
        unsigned* genp = &g_gen[dir];
        unsigned* cntp = &g_cnt[dir];
        unsigned old;
        asm volatile("ld.relaxed.gpu.u32 %0, [%1];" : "=r"(old) : "l"(genp) : "memory");
        unsigned a;
        asm volatile("atom.add.acq_rel.gpu.u32 %0, [%1], 1;" : "=r"(a) : "l"(cntp) : "memory");
        if (a == 63u) {
            asm volatile("st.relaxed.gpu.u32 [%0], 0;" :: "l"(cntp) : "memory");
            asm volatile("st.release.gpu.u32 [%0], %1;" :: "l"(genp), "r"(old + 1u) : "memory");
        } else {
            unsigned g;
            do {
                asm volatile("ld.acquire.gpu.u32 %0, [%1];" : "=r"(g) : "l"(genp) : "memory");
            } while (g == old);
        }
    }
    __syncthreads();
}

// ---------------- persistent bidirectional LSTM, steps [s0, s1) ----------------
// 128 CTAs: dir = bid>>6, ub = bid&63 (8 units). 256 threads = 8 warps.
// K-split: warps 0-3 take kt 0-15, warps 4-7 take kt 16-31, same cols; SMEM reduce.
__global__ __launch_bounds__(256)
void lstm_layer_k(const float* __restrict__ xwf, const float* __restrict__ xwb,
                  const int* __restrict__ tok, __half* __restrict__ y,
                  int layer, int s0, int s1)
{
    extern __shared__ __half smh[];
    uint32_t* swB = (uint32_t*)smh;                  // 32 KB B-frags
    __half*   shh = smh + 16384;                     // 32 x HROW halves
    float*    sred = (float*)(smh + 16384 + 32*HROW); // 4 KB partial sums

    int dir = blockIdx.x >> 6;
    int ub  = blockIdx.x & 63;
    int u0  = ub * 8;
    int tid = threadIdx.x;
    int w   = tid >> 5, lane = tid & 31;
    int wq  = w & 3;                 // column-group warp id
    int half = w >> 2;               // K-half: 0 -> kt 0-15, 1 -> kt 16-31
    int ltid = tid & 127;
    int gid = lane >> 2, tg = lane & 3;

    const float* xw = dir ? xwb : xwf;
    const float* wr = g_wr[layer][dir];

    // ---- pack Wr slice into B-fragment order ----
    for (int i = tid; i < 8192; i += 256) {
        int r  = i & 1;
        int ln = (i >> 1) & 31;
        int w_ = (i >> 6) & 3;
        int kt = i >> 8;
        int n = w_*8 + (ln >> 2);
        int k = kt*16 + r*8 + 2*(ln & 3);
        __half2 hv = __floats2half2_rn(wr[(size_t)k * G4 + u0*4 + n],
                                       wr[(size_t)(k+1) * G4 + u0*4 + n]);
        swB[i] = *(uint32_t*)&hv;
    }

    int uu = u0 + wq*2 + (tg >> 1);
    float cst[4] = {0.f,0.f,0.f,0.f};
    float hst[4] = {0.f,0.f,0.f,0.f};

    if (s0 == 0) {
        for (int i = tid; i < 8*32; i += 256) {
            int bb = i >> 3;
            g_hsh[dir][0][bb * U_ + u0 + (i & 7)] = __float2half_rn(0.f);
        }
    } else if (half == 0) {
        const __half* hread0 = g_hsh[dir][s0 & 1];
#pragma unroll
        for (int j = 0; j < 4; j++) {
            int b = (j >> 1)*16 + gid + (j & 1)*8;
            hst[j] = __half2float(hread0[b * U_ + uu]);
            cst[j] = g_cs[dir][b * U_ + uu];
        }
    }

    grid_barrier(dir);

    for (int s = s0; s < s1; s++) {
        int t = dir ? (T_ - 1 - s) : s;
        const __half* hread  = g_hsh[dir][s & 1];
        __half*       hwrite = g_hsh[dir][(s & 1) ^ 1];

        // ---- prefetch xw gates + masks (warps 0-3 only) ----
        float xwv[2][4];
        int   msk[4];
        if (half == 0) {
#pragma unroll
            for (int j = 0; j < 4; j++) {
                int b = (j >> 1)*16 + gid + (j & 1)*8;
                msk[j] = tok[b * T_ + t];
#pragma unroll
                for (int c = 0; c < 2; c++) {
                    int col = wq*8 + 2*tg + c;
                    int gg = col & 3;
                    int uc = u0 + (col >> 2);
                    xwv[c][j] = xw[((size_t)b * T_ + t) * G4 + gg * U_ + uc];
                }
            }
        }

        // ---- stage h: each warp-group stages only its K-half ----
        for (int i = ltid; i < 1024; i += 128) {
            int row = i >> 5, ch = (i & 31) + half*32;
            cp16(smem_u32(&shh[row * HROW + ch * 8]),
                 hread + row * U_ + ch * 8);
        }
        cp_commit();
        cp_wait<0>();
        asm volatile("bar.sync %0, 128;" :: "r"(1 + half) : "memory");

        // ---- mma: 16 kt per warp-group ----
        float acc[2][4];
#pragma unroll
        for (int mt = 0; mt < 2; mt++)
#pragma unroll
            for (int q = 0; q < 4; q++) acc[mt][q] = 0.f;

        int r8 = lane & 7;
        int quad = lane >> 3;
        uint32_t abase0 = smem_u32(&shh[((quad & 1)*8 + r8) * HROW + (quad >> 1)*8]);
        uint32_t abase1 = abase0 + 16 * HROW * 2;

        int kt0 = half * 16;
#pragma unroll 4
        for (int kt = kt0; kt < kt0 + 16; kt++) {
            uint32_t a0[4], a1[4];
            ldmat_x4(a0, abase0 + kt*32);
            ldmat_x4(a1, abase1 + kt*32);
            uint2 bv = *(const uint2*)&swB[(kt*4 + wq)*64 + lane*2];
            mma_f16(acc[0], a0, bv.x, bv.y);
            mma_f16(acc[1], a1, bv.x, bv.y);
        }

        // ---- reduce K-halves: warps 4-7 store, warps 0-3 add ----
        if (half) {
            float4* d = (float4*)&sred[ltid * 8];
            d[0] = make_float4(acc[0][0], acc[0][1], acc[0][2], acc[0][3]);
            d[1] = make_float4(acc[1][0], acc[1][1], acc[1][2], acc[1][3]);
        }
        __syncthreads();

        if (half == 0) {
            const float4* d = (const float4*)&sred[ltid * 8];
            float4 p0 = d[0], p1 = d[1];
            acc[0][0] += p0.x; acc[0][1] += p0.y; acc[0][2] += p0.z; acc[0][3] += p0.w;
            acc[1][0] += p1.x; acc[1][1] += p1.y; acc[1][2] += p1.z; acc[1][3] += p1.w;

            // ---- add xw, pair-exchange (i,f)/(g,o), cell update ----
            float z[2][4];
#pragma unroll
            for (int mt = 0; mt < 2; mt++)
#pragma unroll
                for (int q = 0; q < 4; q++) {
                    int j = mt*2 + (q >> 1);
                    z[mt][q] = acc[mt][q] + xwv[q & 1][j];
                }

            float rz[2][4];
#pragma unroll
            for (int mt = 0; mt < 2; mt++)
#pragma unroll
                for (int q = 0; q < 4; q++)
                    rz[mt][q] = __shfl_xor_sync(0xffffffffu, z[mt][q], 1);

            if ((tg & 1) == 0) {
#pragma unroll
                for (int j = 0; j < 4; j++) {
                    int mt = j >> 1, qr = (j & 1)*2;
                    float zi = z [mt][qr], zf = z [mt][qr+1];
                    float zg = rz[mt][qr], zo = rz[mt][qr+1];
                    float ig = sigf(zi);
                    float fg = sigf(zf);
                    float gg = tanhfast(zg);
                    float og = sigf(zo);
                    float cn = fg * cst[j] + ig * gg;
                    float hn = og * tanhfast(cn);
                    if (msk[j] != 0) { cst[j] = cn; hst[j] = hn; }
                }
            }

            // ---- packed half2 stores ----
#pragma unroll
            for (int j = 0; j < 4; j++) {
                float oth = __shfl_xor_sync(0xffffffffu, hst[j], 2);
                if (tg == 0) {
                    int b = (j >> 1)*16 + gid + (j & 1)*8;
                    __half2 hp = __floats2half2_rn(hst[j], oth);
                    *(__half2*)&hwrite[b * U_ + uu] = hp;
                    *(__half2*)&y[((size_t)b * T_ + t) * (2*U_) + dir * U_ + uu] = hp;
                }
            }
        }

        grid_barrier(dir);
    }

    // ---- persist c state ----
    if (half == 0 && (tg & 1) == 0) {
#pragma unroll
        for (int j = 0; j < 4; j++) {
            int b = (j >> 1)*16 + gid + (j & 1)*8;
            g_cs[dir][b * U_ + uu] = cst[j];
        }
    }
}

// ---------------- streams/events (created at load time) ----------------
static cudaStream_t g_s2;
static cudaEvent_t  g_ev[10];
static struct InitStreams {
    InitStreams() {
        cudaStreamCreateWithFlags(&g_s2, cudaStreamNonBlocking);
        for (int i = 0; i < 10; i++)
            cudaEventCreateWithFlags(&g_ev[i], cudaEventDisableTiming);
    }
} g_initStreams;

// ---------------- host ----------------
extern "C" void kernel_launch(void* const* d_in, const int* in_sizes, int n_in,
                              void* d_out, int out_size)
{
    const int*   tokens = (const int*)  d_in[0];
    const float* emb    = (const float*)d_in[1];
    const float* k1f    = (const float*)d_in[2];
    const float* r1f    = (const float*)d_in[3];
    const float* b1f    = (const float*)d_in[4];
    const float* k1b    = (const float*)d_in[5];
    const float* r1b    = (const float*)d_in[6];
    const float* b1b    = (const float*)d_in[7];
    const float* k2f    = (const float*)d_in[8];
    const float* r2f    = (const float*)d_in[9];
    const float* b2f    = (const float*)d_in[10];
    const float* k2b    = (const float*)d_in[11];
    const float* r2b    = (const float*)d_in[12];
    const float* b2b    = (const float*)d_in[13];
    const float* wd     = (const float*)d_in[14];
    const float* bd     = (const float*)d_in[15];
    float* out = (float*)d_out;

    static __half *pxh = nullptr, *ph1h, *ph2h;
    static float *pxw0, *pxw1;
    static __half2 *pwdP, *pk1P0, *pk1P1, *pk2P0, *pk2P1;
    if (!pxh) {
        cudaGetSymbolAddress((void**)&pxh,  g_xh);
        cudaGetSymbolAddress((void**)&pxw0, g_xw0);
        cudaGetSymbolAddress((void**)&pxw1, g_xw1);
        cudaGetSymbolAddress((void**)&ph1h, g_h1h);
        cudaGetSymbolAddress((void**)&ph2h, g_h2h);
        cudaGetSymbolAddress((void**)&pwdP, g_wdP);
        cudaGetSymbolAddress((void**)&pk1P0, g_k1P);
        pk1P1 = pk1P0 + (size_t)G4 * E_ / 2;
        cudaGetSymbolAddress((void**)&pk2P0, g_k2P);
        pk2P1 = pk2P0 + (size_t)G4 * 2 * U_ / 2;
        cudaFuncSetAttribute(lstm_layer_k,
                             cudaFuncAttributeMaxDynamicSharedMemorySize,
                             32768 + 32*HROW*2 + 4096);
        cudaFuncSetAttribute(f16_gemm_k,
                             cudaFuncAttributeMaxDynamicSharedMemorySize,
                             4*ASTG*2 + 4*BSTG*4);
    }
    const int lsm = 32768 + 32*HROW*2 + 4096;
    const int gsm = 4*ASTG*2 + 4*BSTG*4;

    cudaEvent_t EA = g_ev[0], EX1M = g_ev[1], EPK = g_ev[2];
    cudaEvent_t EL1A = g_ev[3], EX2M = g_ev[4], EL2A = g_ev[5], ELGM = g_ev[6];

    // ---- prep on main stream ----
    embed_k<<<(BT*E_/8)/256, 256>>>(tokens, emb);
    reorder_k<<<(U_*G4)/256, 256>>>(r1f, r1b, 0);
    reorder_k<<<(U_*G4)/256, 256>>>(r2f, r2b, 1);
    pack_b_k<<<(G4*E_/2)/256, 256>>>(k1f, pk1P0, E_, G4);
    pack_b_k<<<(G4*E_/2)/256, 256>>>(k1b, pk1P1, E_, G4);
    cudaEventRecord(EA, 0);

    // ---- s2: xW1 middle-T, then remaining packs ----
    cudaStreamWaitEvent(g_s2, EA, 0);
    f16_gemm_k<<<dim3(16, 64), 256, gsm, g_s2>>>(pxh, pk1P0, b1f, pxw0, G4, E_, 1);
    f16_gemm_k<<<dim3(16, 64), 256, gsm, g_s2>>>(pxh, pk1P1, b1b, pxw1, G4, E_, 1);
    cudaEventRecord(EX1M, g_s2);
    pack_b_k<<<(G4*2*U_/2)/256, 256, 0, g_s2>>>(k2f, pk2P0, 2*U_, G4);
    pack_b_k<<<(G4*2*U_/2)/256, 256, 0, g_s2>>>(k2b, pk2P1, 2*U_, G4);
    pack_b_k<<<((size_t)VPAD*2*U_/2)/256, 256, 0, g_s2>>>(wd, pwdP, 2*U_, V_);
    cudaEventRecord(EPK, g_s2);

    // ---- main: xW1 outer-T + lstm1 [0,128) ----
    f16_gemm_k<<<dim3(16, 64), 256, gsm>>>(pxh, pk1P0, b1f, pxw0, G4, E_, 2);
    f16_gemm_k<<<dim3(16, 64), 256, gsm>>>(pxh, pk1P1, b1b, pxw1, G4, E_, 2);
    lstm_layer_k<<<128, 256, lsm>>>(pxw0, pxw1, tokens, ph1h, 0, 0, 128);
    cudaStreamWaitEvent(0, EX1M, 0);
    lstm_layer_k<<<128, 256, lsm>>>(pxw0, pxw1, tokens, ph1h, 0, 128, SPLIT);
    cudaEventRecord(EL1A, 0);

    // ---- s2: xW2 middle-T (h1 t in [128,384) final) ----
    cudaStreamWaitEvent(g_s2, EL1A, 0);
    f16_gemm_k<<<dim3(16, 64), 256, gsm, g_s2>>>(ph1h, pk2P0, b2f, pxw0, G4, 2*U_, 1);
    f16_gemm_k<<<dim3(16, 64), 256, gsm, g_s2>>>(ph1h, pk2P1, b2b, pxw1, G4, 2*U_, 1);
    cudaEventRecord(EX2M, g_s2);

    // ---- main: lstm1 part B, xW2 outer-T, lstm2 part A ----
    lstm_layer_k<<<128, 256, lsm>>>(pxw0, pxw1, tokens, ph1h, 0, SPLIT, T_);
    cudaStreamWaitEvent(0, EPK, 0);
    f16_gemm_k<<<dim3(16, 64), 256, gsm>>>(ph1h, pk2P0, b2f, pxw0, G4, 2*U_, 2);
    f16_gemm_k<<<dim3(16, 64), 256, gsm>>>(ph1h, pk2P1, b2b, pxw1, G4, 2*U_, 2);
    cudaStreamWaitEvent(0, EX2M, 0);
    lstm_layer_k<<<128, 256, lsm>>>(pxw0, pxw1, tokens, ph2h, 1, 0, SPLIT);
    cudaEventRecord(EL2A, 0);

    // ---- s2: logits middle-T ----
    cudaStreamWaitEvent(g_s2, EL2A, 0);
    f16_gemm_k<<<dim3(63, 64), 256, gsm, g_s2>>>(ph2h, pwdP, bd, out, V_, 2*U_, 1);
    cudaEventRecord(ELGM, g_s2);

    // ---- main: lstm2 part B, logits outer-T, join ----
    lstm_layer_k<<<128, 256, lsm>>>(pxw0, pxw1, tokens, ph2h, 1, SPLIT, T_);
    f16_gemm_k<<<dim3(63, 64), 256, gsm>>>(ph2h, pwdP, bd, out, V_, 2*U_, 2);
    cudaStreamWaitEvent(0, ELGM, 0);
}

// round 17
// speedup vs baseline: 2.3971x; 1.1735x over previous
#include <cuda_runtime.h>
#include <cuda_fp16.h>
#include <math.h>
#include <stdint.h>

#define B_ 32
#define T_ 512
#define V_ 8000
#define E_ 256
#define U_ 512
#define G4 (4*U_)     // 2048
#define BT (B_*T_)    // 16384
#define VPAD 8064

#define ASTG 5120
#define BSTG 2048
#define HROW 520

// ---------------- static device scratch ----------------
__device__ __half g_xh [BT*E_];
__device__ float  g_xw0[(size_t)BT*G4];
__device__ float  g_xw1[(size_t)BT*G4];
__device__ __half g_h1h[(size_t)BT*2*U_];
__device__ __half g_h2h[(size_t)BT*2*U_];
__device__ float  g_wr [2][2][U_*G4];            // [layer][dir]
__device__ __half g_hsh[2][2][B_*U_];            // [dir][parity]
__device__ float  g_cs [2][B_*U_];               // persisted c state [dir]
__device__ __half2 g_wdP[(size_t)VPAD*2*U_/2];
__device__ __half2 g_k1P[2][(size_t)G4*E_/2];
__device__ __half2 g_k2P[2][(size_t)G4*2*U_/2];
__device__ unsigned g_gen[2];
__device__ unsigned g_cnt[2];

// ---------------- helpers ----------------
__device__ __forceinline__ uint32_t smem_u32(const void* p) {
    uint32_t a;
    asm("{ .reg .u64 t; cvta.to.shared.u64 t, %1; cvt.u32.u64 %0, t; }" : "=r"(a) : "l"(p));
    return a;
}
__device__ __forceinline__ void cp16(uint32_t dst, const void* src) {
    asm volatile("cp.async.ca.shared.global [%0], [%1], 16;" :: "r"(dst), "l"(src));
}
__device__ __forceinline__ void cp_commit() {
    asm volatile("cp.async.commit_group;" ::: "memory");
}
template <int N>
__device__ __forceinline__ void cp_wait() {
    asm volatile("cp.async.wait_group %0;" :: "n"(N) : "memory");
}
__device__ __forceinline__ void mma_f16(float c[4], const uint32_t a[4], uint32_t b0, uint32_t b1) {
    asm volatile(
        "mma.sync.aligned.m16n8k16.row.col.f32.f16.f16.f32 "
        "{%0,%1,%2,%3}, {%4,%5,%6,%7}, {%8,%9}, {%0,%1,%2,%3};"
        : "+f"(c[0]), "+f"(c[1]), "+f"(c[2]), "+f"(c[3])
        : "r"(a[0]), "r"(a[1]), "r"(a[2]), "r"(a[3]), "r"(b0), "r"(b1));
}
__device__ __forceinline__ void ldmat_x4(uint32_t r[4], uint32_t addr) {
    asm volatile("ldmatrix.sync.aligned.m8n8.x4.shared.b16 {%0,%1,%2,%3}, [%4];"
                 : "=r"(r[0]), "=r"(r[1]), "=r"(r[2]), "=r"(r[3]) : "r"(addr));
}
__device__ __forceinline__ float sigf(float x) {
    return __fdividef(1.f, 1.f + __expf(-x));
}
__device__ __forceinline__ float tanhfast(float x) {
    return fmaf(2.f, sigf(2.f * x), -1.f);
}

// ---------------- embedding gather -> fp16 ----------------
__global__ void embed_k(const int* __restrict__ tok, const float* __restrict__ emb) {
    int i = blockIdx.x * 256 + threadIdx.x;
    int row = i >> 5;
    int c8  = i & 31;
    int t = tok[row];
    const float4* s = (const float4*)(emb + (size_t)t * E_ + c8 * 8);
    float4 v0 = s[0], v1 = s[1];
    __half2 h[4];
    h[0] = __floats2half2_rn(v0.x, v0.y);
    h[1] = __floats2half2_rn(v0.z, v0.w);
    h[2] = __floats2half2_rn(v1.x, v1.y);
    h[3] = __floats2half2_rn(v1.z, v1.w);
    *(uint4*)&g_xh[(size_t)row * E_ + c8 * 8] = *(uint4*)h;
}

// ---------------- Wr reorder per layer ----------------
__global__ void reorder_k(const float* __restrict__ rf, const float* __restrict__ rb,
                          int layer) {
    int i = blockIdx.x * 256 + threadIdx.x;
    int k = i / G4;
    int c = i % G4;
    int u = c >> 2, g = c & 3;
    g_wr[layer][0][i] = rf[(size_t)k * G4 + g * U_ + u];
    g_wr[layer][1][i] = rb[(size_t)k * G4 + g * U_ + u];
}

// ---------------- pack B[K][N] -> fp16 fragment order ----------------
__global__ void pack_b_k(const float* __restrict__ in, __half2* __restrict__ out,
                         int K, int N) {
    size_t o = (size_t)blockIdx.x * 256 + threadIdx.x;
    int per_bc = K * 64;
    int bc  = (int)(o / per_bc);
    int rem = (int)(o % per_bc);
    int kt = rem >> 10;
    int r2 = rem & 1023;
    int pg = r2 >> 7;
    int lr = r2 & 127;
    int lane = lr >> 2, r = lr & 3;
    int nt = 2*pg + (r >> 1);
    int breg = r & 1;
    int g = lane >> 2, t4 = lane & 3;
    int k = kt*16 + breg*8 + 2*t4;
    int n = bc*128 + nt*8 + g;
    float v0 = (n < N) ? in[(size_t)k * N + n] : 0.f;
    float v1 = (n < N) ? in[(size_t)(k+1) * N + n] : 0.f;
    out[o] = __floats2half2_rn(v0, v1);
}

// ---------------- fp16 mma band GEMM ----------------
// grid (N/128, 32). CTA = batch by, 128 rows: r<64 -> t=tA+r, r>=64 -> t=tB+r-64.
// Global row = by*T_ + t. Bands need no GMEM contiguity.
__global__ __launch_bounds__(256)
void f16_gemm_k(const __half* __restrict__ Ah, const __half2* __restrict__ Bp,
                const float* __restrict__ bias, float* __restrict__ C,
                int N, int K, int tA, int tB)
{
    extern __shared__ __half sm[];
    __half* As = sm;
    uint32_t* Bs = (uint32_t*)(sm + 4*ASTG);

    int tid = threadIdx.x;
    int wid = tid >> 5, lane = tid & 31;
    int wm = wid >> 1, wn = wid & 1;
    int gid = lane >> 2, tg = lane & 3;
    size_t rowb = (size_t)blockIdx.y * T_;
    int bc = blockIdx.x;
    int colBase = bc * 128;
    const uint32_t* Bsrc = (const uint32_t*)Bp + (size_t)bc * K * 64;

    auto rmap = [&](int r) -> size_t {
        int t = (r < 64) ? (tA + r) : (tB + r - 64);
        return rowb + t;
    };

    float c[2][8][4];
#pragma unroll
    for (int i = 0; i < 2; i++)
#pragma unroll
        for (int j = 0; j < 8; j++)
#pragma unroll
            for (int q = 0; q < 4; q++) c[i][j][q] = 0.f;

    const int nc = K >> 5;

    auto stage = [&](int chunk, int slot) {
#pragma unroll
        for (int it = 0; it < 2; it++) {
            int idx = it * 256 + tid;
            int row = idx >> 2, cq = idx & 3;
            cp16(smem_u32(&As[slot*ASTG + row*40 + cq*8]),
                 Ah + rmap(row) * K + chunk*32 + cq*8);
            cp16(smem_u32(&Bs[slot*BSTG + idx*4]),
                 Bsrc + (size_t)chunk * BSTG + idx*4);
        }
    };

    stage(0, 0); cp_commit();
    stage(1, 1); cp_commit();

    for (int i = 0; i < nc; i++) {
        if (i + 2 < nc) stage(i + 2, (i + 2) & 3);
        cp_commit();
        cp_wait<2>();
        __syncthreads();

        int slot = i & 3;
        const uint32_t* Au = (const uint32_t*)&As[slot*ASTG];
        const uint32_t* Bu = &Bs[slot*BSTG];
#pragma unroll
        for (int kk = 0; kk < 2; kk++) {
            uint32_t af[2][4];
#pragma unroll
            for (int mt = 0; mt < 2; mt++) {
                int rb = (wm*32 + mt*16 + gid)*20 + kk*8 + tg;
                af[mt][0] = Au[rb];
                af[mt][1] = Au[rb + 160];
                af[mt][2] = Au[rb + 4];
                af[mt][3] = Au[rb + 164];
            }
#pragma unroll
            for (int p = 0; p < 4; p++) {
                uint4 bv = *(const uint4*)&Bu[kk*1024 + ((wn*4 + p)*32 + lane)*4];
                mma_f16(c[0][2*p],   af[0], bv.x, bv.y);
                mma_f16(c[0][2*p+1], af[0], bv.z, bv.w);
                mma_f16(c[1][2*p],   af[1], bv.x, bv.y);
                mma_f16(c[1][2*p+1], af[1], bv.z, bv.w);
            }
        }
    }

#pragma unroll
    for (int mt = 0; mt < 2; mt++) {
        int rloc = wm*32 + mt*16 + gid;
        size_t r0 = rmap(rloc);
        size_t r1 = rmap(rloc + 8);
#pragma unroll
        for (int nb = 0; nb < 8; nb++) {
            int col = colBase + wn*64 + nb*8 + tg*2;
            if (col < N) {
                float b0 = bias[col], b1 = bias[col + 1];
                *(float2*)&C[r0 * N + col] =
                    make_float2(c[mt][nb][0] + b0, c[mt][nb][1] + b1);
                *(float2*)&C[r1 * N + col] =
                    make_float2(c[mt][nb][2] + b0, c[mt][nb][3] + b1);
            }
        }
    }
}

// ---------------- software grid barrier (release/acquire) ----------------
__device__ __forceinline__ void grid_barrier(int dir) {
    __syncthreads();
    if (threadIdx.x == 0) {
        unsigned* genp = &g_gen[dir];
        unsigned* cntp = &g_cnt[dir];
        unsigned old;
        asm volatile("ld.relaxed.gpu.u32 %0, [%1];" : "=r"(old) : "l"(genp) : "memory");
        unsigned a;
        asm volatile("atom.add.acq_rel.gpu.u32 %0, [%1], 1;" : "=r"(a) : "l"(cntp) : "memory");
        if (a == 63u) {
            asm volatile("st.relaxed.gpu.u32 [%0], 0;" :: "l"(cntp) : "memory");
            asm volatile("st.release.gpu.u32 [%0], %1;" :: "l"(genp), "r"(old + 1u) : "memory");
        } else {
            unsigned g;
            do {
                asm volatile("ld.acquire.gpu.u32 %0, [%1];" : "=r"(g) : "l"(genp) : "memory");
            } while (g == old);
        }
    }
    __syncthreads();
}

// ---------------- persistent bidirectional LSTM, steps [s0, s1) ----------------
// 128 CTAs, 256 threads; warps 0-3 kt 0-15, warps 4-7 kt 16-31; SMEM reduce.
__global__ __launch_bounds__(256)
void lstm_layer_k(const float* __restrict__ xwf, const float* __restrict__ xwb,
                  const int* __restrict__ tok, __half* __restrict__ y,
                  int layer, int s0, int s1)
{
    extern __shared__ __half smh[];
    uint32_t* swB = (uint32_t*)smh;
    __half*   shh = smh + 16384;
    float*    sred = (float*)(smh + 16384 + 32*HROW);

    int dir = blockIdx.x >> 6;
    int ub  = blockIdx.x & 63;
    int u0  = ub * 8;
    int tid = threadIdx.x;
    int w   = tid >> 5, lane = tid & 31;
    int wq  = w & 3;
    int half = w >> 2;
    int ltid = tid & 127;
    int gid = lane >> 2, tg = lane & 3;

    const float* xw = dir ? xwb : xwf;
    const float* wr = g_wr[layer][dir];

    for (int i = tid; i < 8192; i += 256) {
        int r  = i & 1;
        int ln = (i >> 1) & 31;
        int w_ = (i >> 6) & 3;
        int kt = i >> 8;
        int n = w_*8 + (ln >> 2);
        int k = kt*16 + r*8 + 2*(ln & 3);
        __half2 hv = __floats2half2_rn(wr[(size_t)k * G4 + u0*4 + n],
                                       wr[(size_t)(k+1) * G4 + u0*4 + n]);
        swB[i] = *(uint32_t*)&hv;
    }

    int uu = u0 + wq*2 + (tg >> 1);
    float cst[4] = {0.f,0.f,0.f,0.f};
    float hst[4] = {0.f,0.f,0.f,0.f};

    if (s0 == 0) {
        for (int i = tid; i < 8*32; i += 256) {
            int bb = i >> 3;
            g_hsh[dir][0][bb * U_ + u0 + (i & 7)] = __float2half_rn(0.f);
        }
    } else if (half == 0) {
        const __half* hread0 = g_hsh[dir][s0 & 1];
#pragma unroll
        for (int j = 0; j < 4; j++) {
            int b = (j >> 1)*16 + gid + (j & 1)*8;
            hst[j] = __half2float(hread0[b * U_ + uu]);
            cst[j] = g_cs[dir][b * U_ + uu];
        }
    }

    grid_barrier(dir);

    for (int s = s0; s < s1; s++) {
        int t = dir ? (T_ - 1 - s) : s;
        const __half* hread  = g_hsh[dir][s & 1];
        __half*       hwrite = g_hsh[dir][(s & 1) ^ 1];

        float xwv[2][4];
        int   msk[4];
        if (half == 0) {
#pragma unroll
            for (int j = 0; j < 4; j++) {
                int b = (j >> 1)*16 + gid + (j & 1)*8;
                msk[j] = tok[b * T_ + t];
#pragma unroll
                for (int c = 0; c < 2; c++) {
                    int col = wq*8 + 2*tg + c;
                    int gg = col & 3;
                    int uc = u0 + (col >> 2);
                    xwv[c][j] = xw[((size_t)b * T_ + t) * G4 + gg * U_ + uc];
                }
            }
        }

        for (int i = ltid; i < 1024; i += 128) {
            int row = i >> 5, ch = (i & 31) + half*32;
            cp16(smem_u32(&shh[row * HROW + ch * 8]),
                 hread + row * U_ + ch * 8);
        }
        cp_commit();
        cp_wait<0>();
        asm volatile("bar.sync %0, 128;" :: "r"(1 + half) : "memory");

        float acc[2][4];
#pragma unroll
        for (int mt = 0; mt < 2; mt++)
#pragma unroll
            for (int q = 0; q < 4; q++) acc[mt][q] = 0.f;

        int r8 = lane & 7;
        int quad = lane >> 3;
        uint32_t abase0 = smem_u32(&shh[((quad & 1)*8 + r8) * HROW + (quad >> 1)*8]);
        uint32_t abase1 = abase0 + 16 * HROW * 2;

        int kt0 = half * 16;
#pragma unroll 4
        for (int kt = kt0; kt < kt0 + 16; kt++) {
            uint32_t a0[4], a1[4];
            ldmat_x4(a0, abase0 + kt*32);
            ldmat_x4(a1, abase1 + kt*32);
            uint2 bv = *(const uint2*)&swB[(kt*4 + wq)*64 + lane*2];
            mma_f16(acc[0], a0, bv.x, bv.y);
            mma_f16(acc[1], a1, bv.x, bv.y);
        }

        if (half) {
            float4* d = (float4*)&sred[ltid * 8];
            d[0] = make_float4(acc[0][0], acc[0][1], acc[0][2], acc[0][3]);
            d[1] = make_float4(acc[1][0], acc[1][1], acc[1][2], acc[1][3]);
        }
        __syncthreads();

        if (half == 0) {
            const float4* d = (const float4*)&sred[ltid * 8];
            float4 p0 = d[0], p1 = d[1];
            acc[0][0] += p0.x; acc[0][1] += p0.y; acc[0][2] += p0.z; acc[0][3] += p0.w;
            acc[1][0] += p1.x; acc[1][1] += p1.y; acc[1][2] += p1.z; acc[1][3] += p1.w;

            float z[2][4];
#pragma unroll
            for (int mt = 0; mt < 2; mt++)
#pragma unroll
                for (int q = 0; q < 4; q++) {
                    int j = mt*2 + (q >> 1);
                    z[mt][q] = acc[mt][q] + xwv[q & 1][j];
                }

            float rz[2][4];
#pragma unroll
            for (int mt = 0; mt < 2; mt++)
#pragma unroll
                for (int q = 0; q < 4; q++)
                    rz[mt][q] = __shfl_xor_sync(0xffffffffu, z[mt][q], 1);

            if ((tg & 1) == 0) {
#pragma unroll
                for (int j = 0; j < 4; j++) {
                    int mt = j >> 1, qr = (j & 1)*2;
                    float zi = z [mt][qr], zf = z [mt][qr+1];
                    float zg = rz[mt][qr], zo = rz[mt][qr+1];
                    float ig = sigf(zi);
                    float fg = sigf(zf);
                    float gg = tanhfast(zg);
                    float og = sigf(zo);
                    float cn = fg * cst[j] + ig * gg;
                    float hn = og * tanhfast(cn);
                    if (msk[j] != 0) { cst[j] = cn; hst[j] = hn; }
                }
            }

#pragma unroll
            for (int j = 0; j < 4; j++) {
                float oth = __shfl_xor_sync(0xffffffffu, hst[j], 2);
                if (tg == 0) {
                    int b = (j >> 1)*16 + gid + (j & 1)*8;
                    __half2 hp = __floats2half2_rn(hst[j], oth);
                    *(__half2*)&hwrite[b * U_ + uu] = hp;
                    *(__half2*)&y[((size_t)b * T_ + t) * (2*U_) + dir * U_ + uu] = hp;
                }
            }
        }

        grid_barrier(dir);
    }

    if (half == 0 && (tg & 1) == 0) {
#pragma unroll
        for (int j = 0; j < 4; j++) {
            int b = (j >> 1)*16 + gid + (j & 1)*8;
            g_cs[dir][b * U_ + uu] = cst[j];
        }
    }
}

// ---------------- streams/events (created at load time) ----------------
static cudaStream_t g_s2;
static cudaEvent_t  g_ev[12];
static struct InitStreams {
    InitStreams() {
        cudaStreamCreateWithFlags(&g_s2, cudaStreamNonBlocking);
        for (int i = 0; i < 12; i++)
            cudaEventCreateWithFlags(&g_ev[i], cudaEventDisableTiming);
    }
} g_initStreams;

// ---------------- host ----------------
extern "C" void kernel_launch(void* const* d_in, const int* in_sizes, int n_in,
                              void* d_out, int out_size)
{
    const int*   tokens = (const int*)  d_in[0];
    const float* emb    = (const float*)d_in[1];
    const float* k1f    = (const float*)d_in[2];
    const float* r1f    = (const float*)d_in[3];
    const float* b1f    = (const float*)d_in[4];
    const float* k1b    = (const float*)d_in[5];
    const float* r1b    = (const float*)d_in[6];
    const float* b1b    = (const float*)d_in[7];
    const float* k2f    = (const float*)d_in[8];
    const float* r2f    = (const float*)d_in[9];
    const float* b2f    = (const float*)d_in[10];
    const float* k2b    = (const float*)d_in[11];
    const float* r2b    = (const float*)d_in[12];
    const float* b2b    = (const float*)d_in[13];
    const float* wd     = (const float*)d_in[14];
    const float* bd     = (const float*)d_in[15];
    float* out = (float*)d_out;

    static __half *pxh = nullptr, *ph1h, *ph2h;
    static float *pxw0, *pxw1;
    static __half2 *pwdP, *pk1P0, *pk1P1, *pk2P0, *pk2P1;
    if (!pxh) {
        cudaGetSymbolAddress((void**)&pxh,  g_xh);
        cudaGetSymbolAddress((void**)&pxw0, g_xw0);
        cudaGetSymbolAddress((void**)&pxw1, g_xw1);
        cudaGetSymbolAddress((void**)&ph1h, g_h1h);
        cudaGetSymbolAddress((void**)&ph2h, g_h2h);
        cudaGetSymbolAddress((void**)&pwdP, g_wdP);
        cudaGetSymbolAddress((void**)&pk1P0, g_k1P);
        pk1P1 = pk1P0 + (size_t)G4 * E_ / 2;
        cudaGetSymbolAddress((void**)&pk2P0, g_k2P);
        pk2P1 = pk2P0 + (size_t)G4 * 2 * U_ / 2;
        cudaFuncSetAttribute(lstm_layer_k,
                             cudaFuncAttributeMaxDynamicSharedMemorySize,
                             32768 + 32*HROW*2 + 4096);
        cudaFuncSetAttribute(f16_gemm_k,
                             cudaFuncAttributeMaxDynamicSharedMemorySize,
                             4*ASTG*2 + 4*BSTG*4);
    }
    const int lsm = 32768 + 32*HROW*2 + 4096;
    const int gsm = 4*ASTG*2 + 4*BSTG*4;

    cudaEvent_t EA = g_ev[0], EX1M = g_ev[1], EPK = g_ev[2];
    cudaEvent_t EL1a = g_ev[3], EL1b = g_ev[4], EL1c = g_ev[5], EXW2S = g_ev[6];
    cudaEvent_t EL2a = g_ev[7], EL2b = g_ev[8], EL2c = g_ev[9], ELGS = g_ev[10];

    // ---- prep on main stream ----
    embed_k<<<(BT*E_/8)/256, 256>>>(tokens, emb);
    reorder_k<<<(U_*G4)/256, 256>>>(r1f, r1b, 0);
    reorder_k<<<(U_*G4)/256, 256>>>(r2f, r2b, 1);
    pack_b_k<<<(G4*E_/2)/256, 256>>>(k1f, pk1P0, E_, G4);
    pack_b_k<<<(G4*E_/2)/256, 256>>>(k1b, pk1P1, E_, G4);
    cudaEventRecord(EA, 0);

    // ---- s2: xW1 middle bands, then remaining packs ----
    cudaStreamWaitEvent(g_s2, EA, 0);
    f16_gemm_k<<<dim3(16, 32), 256, gsm, g_s2>>>(pxh, pk1P0, b1f, pxw0, G4, E_, 128, 256);
    f16_gemm_k<<<dim3(16, 32), 256, gsm, g_s2>>>(pxh, pk1P1, b1b, pxw1, G4, E_, 128, 256);
    f16_gemm_k<<<dim3(16, 32), 256, gsm, g_s2>>>(pxh, pk1P0, b1f, pxw0, G4, E_, 192, 320);
    f16_gemm_k<<<dim3(16, 32), 256, gsm, g_s2>>>(pxh, pk1P1, b1b, pxw1, G4, E_, 192, 320);
    cudaEventRecord(EX1M, g_s2);
    pack_b_k<<<(G4*2*U_/2)/256, 256, 0, g_s2>>>(k2f, pk2P0, 2*U_, G4);
    pack_b_k<<<(G4*2*U_/2)/256, 256, 0, g_s2>>>(k2b, pk2P1, 2*U_, G4);
    pack_b_k<<<((size_t)VPAD*2*U_/2)/256, 256, 0, g_s2>>>(wd, pwdP, 2*U_, V_);
    cudaEventRecord(EPK, g_s2);

    // ---- main: xW1 outer bands + lstm1 [0,128) ----
    f16_gemm_k<<<dim3(16, 32), 256, gsm>>>(pxh, pk1P0, b1f, pxw0, G4, E_, 0, 448);
    f16_gemm_k<<<dim3(16, 32), 256, gsm>>>(pxh, pk1P1, b1b, pxw1, G4, E_, 0, 448);
    f16_gemm_k<<<dim3(16, 32), 256, gsm>>>(pxh, pk1P0, b1f, pxw0, G4, E_, 64, 384);
    f16_gemm_k<<<dim3(16, 32), 256, gsm>>>(pxh, pk1P1, b1b, pxw1, G4, E_, 64, 384);
    lstm_layer_k<<<128, 256, lsm>>>(pxw0, pxw1, tokens, ph1h, 0, 0, 128);
    cudaStreamWaitEvent(0, EX1M, 0);
    lstm_layer_k<<<128, 256, lsm>>>(pxw0, pxw1, tokens, ph1h, 0, 128, 320);
    cudaEventRecord(EL1a, 0);
    lstm_layer_k<<<128, 256, lsm>>>(pxw0, pxw1, tokens, ph1h, 0, 320, 384);
    cudaEventRecord(EL1b, 0);
    lstm_layer_k<<<128, 256, lsm>>>(pxw0, pxw1, tokens, ph1h, 0, 384, 448);
    cudaEventRecord(EL1c, 0);
    lstm_layer_k<<<128, 256, lsm>>>(pxw0, pxw1, tokens, ph1h, 0, 448, T_);

    // ---- s2: xW2 streamed chunks as h1 bands finalize ----
    cudaStreamWaitEvent(g_s2, EL1a, 0);
    f16_gemm_k<<<dim3(16, 32), 256, gsm, g_s2>>>(ph1h, pk2P0, b2f, pxw0, G4, 2*U_, 192, 256);
    f16_gemm_k<<<dim3(16, 32), 256, gsm, g_s2>>>(ph1h, pk2P1, b2b, pxw1, G4, 2*U_, 192, 256);
    cudaStreamWaitEvent(g_s2, EL1b, 0);
    f16_gemm_k<<<dim3(16, 32), 256, gsm, g_s2>>>(ph1h, pk2P0, b2f, pxw0, G4, 2*U_, 128, 320);
    f16_gemm_k<<<dim3(16, 32), 256, gsm, g_s2>>>(ph1h, pk2P1, b2b, pxw1, G4, 2*U_, 128, 320);
    cudaStreamWaitEvent(g_s2, EL1c, 0);
    f16_gemm_k<<<dim3(16, 32), 256, gsm, g_s2>>>(ph1h, pk2P0, b2f, pxw0, G4, 2*U_, 64, 384);
    f16_gemm_k<<<dim3(16, 32), 256, gsm, g_s2>>>(ph1h, pk2P1, b2b, pxw1, G4, 2*U_, 64, 384);
    cudaEventRecord(EXW2S, g_s2);

    // ---- main: xW2 edge chunk (h1 edges final now), then lstm2 segments ----
    cudaStreamWaitEvent(0, EPK, 0);
    f16_gemm_k<<<dim3(16, 32), 256, gsm>>>(ph1h, pk2P0, b2f, pxw0, G4, 2*U_, 0, 448);
    f16_gemm_k<<<dim3(16, 32), 256, gsm>>>(ph1h, pk2P1, b2b, pxw1, G4, 2*U_, 0, 448);
    cudaStreamWaitEvent(0, EXW2S, 0);
    lstm_layer_k<<<128, 256, lsm>>>(pxw0, pxw1, tokens, ph2h, 1, 0, 320);
    cudaEventRecord(EL2a, 0);
    lstm_layer_k<<<128, 256, lsm>>>(pxw0, pxw1, tokens, ph2h, 1, 320, 384);
    cudaEventRecord(EL2b, 0);
    lstm_layer_k<<<128, 256, lsm>>>(pxw0, pxw1, tokens, ph2h, 1, 384, 448);
    cudaEventRecord(EL2c, 0);
    lstm_layer_k<<<128, 256, lsm>>>(pxw0, pxw1, tokens, ph2h, 1, 448, T_);

    // ---- s2: logits streamed chunks ----
    cudaStreamWaitEvent(g_s2, EL2a, 0);
    f16_gemm_k<<<dim3(63, 32), 256, gsm, g_s2>>>(ph2h, pwdP, bd, out, V_, 2*U_, 192, 256);
    cudaStreamWaitEvent(g_s2, EL2b, 0);
    f16_gemm_k<<<dim3(63, 32), 256, gsm, g_s2>>>(ph2h, pwdP, bd, out, V_, 2*U_, 128, 320);
    cudaStreamWaitEvent(g_s2, EL2c, 0);
    f16_gemm_k<<<dim3(63, 32), 256, gsm, g_s2>>>(ph2h, pwdP, bd, out, V_, 2*U_, 64, 384);
    cudaEventRecord(ELGS, g_s2);

    // ---- main: logits edge chunk, join ----
    f16_gemm_k<<<dim3(63, 32), 256, gsm>>>(ph2h, pwdP, bd, out, V_, 2*U_, 0, 448);
    cudaStreamWaitEvent(0, ELGS, 0);
}